// round 5
// baseline (speedup 1.0000x reference)
#include <cuda_runtime.h>
#include <math.h>

#define SEQ 128
#define BATCH 32
#define NHID 512
#define NVOC 32000
#define M_ROWS (SEQ * BATCH)                 /* 4096 */
#define HID_OFF ((size_t)M_ROWS * NVOC)      /* 131072000 */
#define LSTM_GRID 128
#define HS 516                               /* padded h_sm row stride (floats) */

/* smem partition (floats) for lstm kernel */
#define OFF_W0 0
#define OFF_W1 (OFF_W0 + 16 * 512)
#define OFF_H  (OFF_W1 + 16 * 1024)
#define OFF_A  (OFF_H + 32 * HS)
#define OFF_B1 (OFF_A + 16 * 32)
#define SMEM_FLOATS (OFF_B1 + 16)
#define SMEM_BYTES (SMEM_FLOATS * 4)         /* 166464 B */

// ------------------------- device scratch (no allocs allowed) ----------------
__device__ float g_embT[(size_t)NHID * M_ROWS];       // emb^T  [512][4096]
__device__ float g_g0xT[(size_t)4 * NHID * M_ROWS];   // layer0 x-gates^T [2048][4096]
__device__ float g_outT[(size_t)NHID * M_ROWS];       // h1 out^T [512][4096]
__device__ float g_h0[2][BATCH * NHID];               // [parity][b*512 + k]
__device__ float g_h1[2][BATCH * NHID];
__device__ unsigned g_count = 0;
__device__ unsigned g_epoch = 0;

// ------------------------- embedding gather ----------------------------------
__global__ void embed_kernel(const int* __restrict__ tok,
                             const float* __restrict__ embW) {
  int idx = blockIdx.x * 256 + threadIdx.x;
  if (idx >= NHID * M_ROWS) return;
  int m = idx & (M_ROWS - 1);
  int k = idx >> 12;
  g_embT[idx] = embW[(size_t)tok[m] * NHID + k];
}

// ------------------------- SGEMM: C = A * B^T + bias -------------------------
// AT[k][m] (lda == M).  B row-major [n][ldb].
// TRANSC=false: C[m][n] stride ldc.  TRANSC=true: C[n][m] stride ldc.
template <bool TRANSC>
__global__ void __launch_bounds__(256, 1)
sgemm_atn(const float* __restrict__ AT, const float* __restrict__ B, int ldb,
          const float* __restrict__ bias, float* __restrict__ C, int ldc,
          int M, int N, int K) {
  __shared__ float As[16][128];
  __shared__ float Bs[16][128];
  const int m0 = blockIdx.x * 128, n0 = blockIdx.y * 128;
  const int tid = threadIdx.x;
  const int tr = tid >> 4, tc = tid & 15;

  float acc[8][8];
#pragma unroll
  for (int i = 0; i < 8; i++)
#pragma unroll
    for (int j = 0; j < 8; j++) acc[i][j] = 0.f;

  const int ka = tid >> 5;          // 0..7
  const int ma = (tid & 31) << 2;   // 0..124
  const int nb = tid >> 1;          // 0..127
  const int kb = (tid & 1) << 3;    // 0 or 8

  for (int k0 = 0; k0 < K; k0 += 16) {
    float4 a0 = *(const float4*)&AT[(size_t)(k0 + ka) * M + m0 + ma];
    float4 a1 = *(const float4*)&AT[(size_t)(k0 + ka + 8) * M + m0 + ma];
    float4 b0 = *(const float4*)&B[(size_t)(n0 + nb) * ldb + k0 + kb];
    float4 b1 = *(const float4*)&B[(size_t)(n0 + nb) * ldb + k0 + kb + 4];
    __syncthreads();
    *(float4*)&As[ka][ma] = a0;
    *(float4*)&As[ka + 8][ma] = a1;
    Bs[kb + 0][nb] = b0.x; Bs[kb + 1][nb] = b0.y;
    Bs[kb + 2][nb] = b0.z; Bs[kb + 3][nb] = b0.w;
    Bs[kb + 4][nb] = b1.x; Bs[kb + 5][nb] = b1.y;
    Bs[kb + 6][nb] = b1.z; Bs[kb + 7][nb] = b1.w;
    __syncthreads();
#pragma unroll
    for (int kk = 0; kk < 16; ++kk) {
      float a[8], bq[8];
      *(float4*)&a[0] = *(const float4*)&As[kk][tr * 8];
      *(float4*)&a[4] = *(const float4*)&As[kk][tr * 8 + 4];
      *(float4*)&bq[0] = *(const float4*)&Bs[kk][tc * 8];
      *(float4*)&bq[4] = *(const float4*)&Bs[kk][tc * 8 + 4];
#pragma unroll
      for (int i = 0; i < 8; i++)
#pragma unroll
        for (int j = 0; j < 8; j++) acc[i][j] += a[i] * bq[j];
    }
  }

  if (!TRANSC) {
#pragma unroll
    for (int i = 0; i < 8; i++) {
      int m = m0 + tr * 8 + i;
#pragma unroll
      for (int j = 0; j < 8; j += 4) {
        int n = n0 + tc * 8 + j;
        float4 v;
        v.x = acc[i][j + 0] + bias[n + 0];
        v.y = acc[i][j + 1] + bias[n + 1];
        v.z = acc[i][j + 2] + bias[n + 2];
        v.w = acc[i][j + 3] + bias[n + 3];
        *(float4*)&C[(size_t)m * ldc + n] = v;
      }
    }
  } else {
#pragma unroll
    for (int j = 0; j < 8; j++) {
      int n = n0 + tc * 8 + j;
      float bv = bias[n];
#pragma unroll
      for (int i = 0; i < 8; i += 4) {
        float4 v;
        v.x = acc[i + 0][j] + bv;
        v.y = acc[i + 1][j] + bv;
        v.z = acc[i + 2][j] + bv;
        v.w = acc[i + 3][j] + bv;
        *(float4*)&C[(size_t)n * ldc + m0 + tr * 8 + i] = v;
      }
    }
  }
}

// ------------------------- persistent LSTM recurrence ------------------------
__device__ __forceinline__ void gridbar() {
  __threadfence();
  __syncthreads();
  if (threadIdx.x == 0) {
    unsigned e = *(volatile unsigned*)&g_epoch;
    __threadfence();
    unsigned prev = atomicAdd(&g_count, 1u);
    if (prev == (unsigned)(LSTM_GRID - 1)) {
      atomicExch(&g_count, 0u);
      __threadfence();
      atomicAdd(&g_epoch, 1u);
    } else {
      while (*(volatile unsigned*)&g_epoch == e) __nanosleep(64);
    }
    __threadfence();
  }
  __syncthreads();
}

__device__ __forceinline__ void stage_h(float* h_sm, const float* __restrict__ src) {
  // src: [32][512] row-major -> h_sm: [32][HS]
  for (int i = threadIdx.x; i < 4096; i += 256) {
    int b = i >> 7;
    int k4 = (i & 127) << 2;
    float4 v = *(const float4*)(src + b * 512 + k4);
    *(float4*)(h_sm + b * HS + k4) = v;
  }
}

__device__ __forceinline__ void accum512(const float* __restrict__ Wr0,
                                         const float* __restrict__ Wr1,
                                         const float* __restrict__ hrow,
                                         float& acc0, float& acc1) {
#pragma unroll 4
  for (int k = 0; k < 512; k += 4) {
    float4 hv = *(const float4*)(hrow + k);
    float4 w0 = *(const float4*)(Wr0 + k);
    float4 w1 = *(const float4*)(Wr1 + k);
    acc0 += w0.x * hv.x; acc1 += w1.x * hv.x;
    acc0 += w0.y * hv.y; acc1 += w1.y * hv.y;
    acc0 += w0.z * hv.z; acc1 += w1.z * hv.z;
    acc0 += w0.w * hv.w; acc1 += w1.w * hv.w;
  }
}

__device__ __forceinline__ float sigm(float x) { return 1.f / (1.f + __expf(-x)); }

__global__ void __launch_bounds__(256, 1)
lstm_kernel(const float* __restrict__ fcW, const float* __restrict__ fcb,
            float* __restrict__ out) {
  extern __shared__ float sm[];
  float* W0s = sm + OFF_W0;   // 16 rows x 512
  float* W1s = sm + OFF_W1;   // 16 rows x 1024
  float* h_sm = sm + OFF_H;   // 32 x HS
  float* a_sm = sm + OFF_A;   // 16 x 32
  float* b1s = sm + OFF_B1;   // 16

  const int tid = threadIdx.x;
  const int w = tid >> 5;
  const int lane = tid & 31;
  const int cta = blockIdx.x;

  // ---- load weight slices into smem (once) ----
  // local row r -> unit j=r>>2, gate g=r&3 -> global gate row gr = cta*4 + j + g*512
  for (int i = tid; i < 16 * 512; i += 256) {
    int r = i >> 9, k = i & 511;
    int gr = cta * 4 + (r >> 2) + (r & 3) * 512;
    W0s[i] = fcW[(size_t)gr * 1024 + 512 + k];               // layer0 h-part
  }
  for (int i = tid; i < 16 * 1024; i += 256) {
    int r = i >> 10, k = i & 1023;
    int gr = cta * 4 + (r >> 2) + (r & 3) * 512;
    W1s[i] = fcW[(size_t)2048 * 1024 + (size_t)gr * 1024 + k];  // layer1 full
  }
  if (tid < 16)
    b1s[tid] = fcb[2048 + cta * 4 + (tid >> 2) + (tid & 3) * 512];

  // ---- zero initial hidden state (all parities, both layers) ----
  {
    int g = cta * 256 + tid;
    if (g < BATCH * NHID) {
      g_h0[0][g] = 0.f; g_h0[1][g] = 0.f;
      g_h1[0][g] = 0.f; g_h1[1][g] = 0.f;
    }
  }
  gridbar();

  float c0r = 0.f, c1r = 0.f;   // cell state (meaningful for warps 0..3, lane=batch)
  const int U = cta * 4 + (w & 3);
  float* hid = out + HID_OFF;

  for (int t = 0; t < SEQ; ++t) {
    const int p = t & 1;
    const int m = t * 32 + lane;

    // ================= phase A: layer 0 (h-part + precomputed x-part) ========
    stage_h(h_sm, &g_h0[p][0]);
    __syncthreads();
    {
      float a0 = 0.f, a1 = 0.f;
      accum512(W0s + (2 * w) * 512, W0s + (2 * w + 1) * 512,
               h_sm + lane * HS, a0, a1);
      a_sm[(2 * w) * 32 + lane] = a0;
      a_sm[(2 * w + 1) * 32 + lane] = a1;
    }
    __syncthreads();
    if (w < 4) {
      float a[4];
#pragma unroll
      for (int g = 0; g < 4; ++g)
        a[g] = a_sm[(w * 4 + g) * 32 + lane] +
               g_g0xT[(size_t)(U + g * 512) * M_ROWS + m];
      float ig = sigm(a[0]), fg = sigm(a[1]), og = sigm(a[2]);
      float bg = tanhf(a[3]);
      c0r = fg * c0r + ig * bg;
      float h0v = og * tanhf(c0r);
      g_h0[p ^ 1][lane * 512 + U] = h0v;
      if (t == SEQ - 1) hid[lane * 512 + U] = h0v;   // hidden layer 0
    }
    gridbar();

    // ================= phase B: layer 1 (K=1024 in two 512 chunks) ===========
    stage_h(h_sm, &g_h0[p ^ 1][0]);    // chunk 0: h0_new
    __syncthreads();
    float a0 = 0.f, a1 = 0.f;
    accum512(W1s + (2 * w) * 1024, W1s + (2 * w + 1) * 1024,
             h_sm + lane * HS, a0, a1);
    __syncthreads();                   // everyone done reading chunk 0
    stage_h(h_sm, &g_h1[p][0]);        // chunk 1: h1_prev
    __syncthreads();
    accum512(W1s + (2 * w) * 1024 + 512, W1s + (2 * w + 1) * 1024 + 512,
             h_sm + lane * HS, a0, a1);
    a_sm[(2 * w) * 32 + lane] = a0;
    a_sm[(2 * w + 1) * 32 + lane] = a1;
    __syncthreads();
    if (w < 4) {
      float a[4];
#pragma unroll
      for (int g = 0; g < 4; ++g)
        a[g] = a_sm[(w * 4 + g) * 32 + lane] + b1s[w * 4 + g];
      float ig = sigm(a[0]), fg = sigm(a[1]), og = sigm(a[2]);
      float bg = tanhf(a[3]);
      c1r = fg * c1r + ig * bg;
      float h1v = og * tanhf(c1r);
      g_h1[p ^ 1][lane * 512 + U] = h1v;
      g_outT[(size_t)U * M_ROWS + m] = h1v;
      if (t == SEQ - 1) hid[16384 + lane * 512 + U] = h1v;  // hidden layer 1
    }
    gridbar();
  }
}

// ------------------------- launch ------------------------------------------
extern "C" void kernel_launch(void* const* d_in, const int* in_sizes, int n_in,
                              void* d_out, int out_size) {
  const int* tok = (const int*)d_in[0];
  const float* embW = (const float*)d_in[1];
  const float* fcW = (const float*)d_in[2];
  const float* fcb = (const float*)d_in[3];
  const float* decW = (const float*)d_in[4];
  const float* decb = (const float*)d_in[5];
  float* out = (float*)d_out;

  void *p_embT = 0, *p_g0xT = 0, *p_outT = 0;
  cudaGetSymbolAddress(&p_embT, g_embT);
  cudaGetSymbolAddress(&p_g0xT, g_g0xT);
  cudaGetSymbolAddress(&p_outT, g_outT);

  // 1) embedding gather -> embT
  embed_kernel<<<(NHID * M_ROWS + 255) / 256, 256>>>(tok, embW);

  // 2) layer-0 input projection for all timesteps: g0xT[g][m]
  //    M=4096 (m), N=2048 (gate rows), K=512 (input part of fcW layer 0)
  sgemm_atn<true><<<dim3(M_ROWS / 128, 2048 / 128), 256>>>(
      (const float*)p_embT, fcW, 1024, fcb,
      (float*)p_g0xT, M_ROWS, M_ROWS, 2048, NHID);

  // 3) persistent LSTM recurrence (both layers), writes outT + hidden state
  cudaFuncSetAttribute(lstm_kernel,
                       cudaFuncAttributeMaxDynamicSharedMemorySize, SMEM_BYTES);
  lstm_kernel<<<LSTM_GRID, 256, SMEM_BYTES>>>(fcW, fcb, out);

  // 4) decoder: decoded[m][v] = outT^T . decW^T + decb
  sgemm_atn<false><<<dim3(M_ROWS / 128, NVOC / 128), 256>>>(
      (const float*)p_outT, decW, NHID, decb,
      out, NVOC, M_ROWS, NVOC, NHID);
}

// round 7
// speedup vs baseline: 1.3143x; 1.3143x over previous
#include <cuda_runtime.h>
#include <cuda_bf16.h>
#include <math.h>
#include <stdint.h>

#define SEQ 128
#define BATCH 32
#define NHID 512
#define NVOC 32000
#define M_ROWS (SEQ * BATCH)                 /* 4096 */
#define HID_OFF ((size_t)M_ROWS * NVOC)      /* 131072000 */
#define LSTM_GRID 128
#define HS 516                               /* padded h_sm row stride (floats) */

/* smem partition (floats) for lstm kernel */
#define OFF_W0 0
#define OFF_W1 (OFF_W0 + 16 * 512)
#define OFF_H  (OFF_W1 + 16 * 1024)
#define OFF_A  (OFF_H + 32 * HS)
#define OFF_B1 (OFF_A + 16 * 32)
#define SMEM_FLOATS (OFF_B1 + 16)
#define SMEM_BYTES (SMEM_FLOATS * 4)

// ------------------------- device scratch (no allocs allowed) ----------------
__device__ float g_embT[(size_t)NHID * M_ROWS];       // emb^T  [512][4096]
__device__ float g_g0xT[(size_t)4 * NHID * M_ROWS];   // layer0 x-gates^T [2048][4096]
__device__ float g_outT[(size_t)NHID * M_ROWS];       // h1 out^T [512][4096]
__device__ float g_h0[2][BATCH * NHID];
__device__ float g_h1[2][BATCH * NHID];
__device__ unsigned g_count = 0;
__device__ unsigned g_epoch = 0;

// split-bf16 operands for the tensor-core decoder
__device__ __nv_bfloat16 g_Ahi[(size_t)M_ROWS * NHID];
__device__ __nv_bfloat16 g_Alo[(size_t)M_ROWS * NHID];
__device__ __nv_bfloat16 g_Bhi[(size_t)NVOC * NHID];
__device__ __nv_bfloat16 g_Blo[(size_t)NVOC * NHID];

// ------------------------- embedding gather ----------------------------------
__global__ void embed_kernel(const int* __restrict__ tok,
                             const float* __restrict__ embW) {
  int idx = blockIdx.x * 256 + threadIdx.x;
  if (idx >= NHID * M_ROWS) return;
  int m = idx & (M_ROWS - 1);
  int k = idx >> 12;
  g_embT[idx] = embW[(size_t)tok[m] * NHID + k];
}

// ------------------------- SGEMM: C = A * B^T + bias (gemm0 only) -----------
template <bool TRANSC>
__global__ void __launch_bounds__(256, 1)
sgemm_atn(const float* __restrict__ AT, const float* __restrict__ B, int ldb,
          const float* __restrict__ bias, float* __restrict__ C, int ldc,
          int M, int N, int K) {
  __shared__ float As[16][128];
  __shared__ float Bs[16][128];
  const int m0 = blockIdx.x * 128, n0 = blockIdx.y * 128;
  const int tid = threadIdx.x;
  const int tr = tid >> 4, tc = tid & 15;

  float acc[8][8];
#pragma unroll
  for (int i = 0; i < 8; i++)
#pragma unroll
    for (int j = 0; j < 8; j++) acc[i][j] = 0.f;

  const int ka = tid >> 5;
  const int ma = (tid & 31) << 2;
  const int nb = tid >> 1;
  const int kb = (tid & 1) << 3;

  for (int k0 = 0; k0 < K; k0 += 16) {
    float4 a0 = *(const float4*)&AT[(size_t)(k0 + ka) * M + m0 + ma];
    float4 a1 = *(const float4*)&AT[(size_t)(k0 + ka + 8) * M + m0 + ma];
    float4 b0 = *(const float4*)&B[(size_t)(n0 + nb) * ldb + k0 + kb];
    float4 b1 = *(const float4*)&B[(size_t)(n0 + nb) * ldb + k0 + kb + 4];
    __syncthreads();
    *(float4*)&As[ka][ma] = a0;
    *(float4*)&As[ka + 8][ma] = a1;
    Bs[kb + 0][nb] = b0.x; Bs[kb + 1][nb] = b0.y;
    Bs[kb + 2][nb] = b0.z; Bs[kb + 3][nb] = b0.w;
    Bs[kb + 4][nb] = b1.x; Bs[kb + 5][nb] = b1.y;
    Bs[kb + 6][nb] = b1.z; Bs[kb + 7][nb] = b1.w;
    __syncthreads();
#pragma unroll
    for (int kk = 0; kk < 16; ++kk) {
      float a[8], bq[8];
      *(float4*)&a[0] = *(const float4*)&As[kk][tr * 8];
      *(float4*)&a[4] = *(const float4*)&As[kk][tr * 8 + 4];
      *(float4*)&bq[0] = *(const float4*)&Bs[kk][tc * 8];
      *(float4*)&bq[4] = *(const float4*)&Bs[kk][tc * 8 + 4];
#pragma unroll
      for (int i = 0; i < 8; i++)
#pragma unroll
        for (int j = 0; j < 8; j++) acc[i][j] += a[i] * bq[j];
    }
  }

  if (!TRANSC) {
#pragma unroll
    for (int i = 0; i < 8; i++) {
      int m = m0 + tr * 8 + i;
#pragma unroll
      for (int j = 0; j < 8; j += 4) {
        int n = n0 + tc * 8 + j;
        float4 v;
        v.x = acc[i][j + 0] + bias[n + 0];
        v.y = acc[i][j + 1] + bias[n + 1];
        v.z = acc[i][j + 2] + bias[n + 2];
        v.w = acc[i][j + 3] + bias[n + 3];
        *(float4*)&C[(size_t)m * ldc + n] = v;
      }
    }
  } else {
#pragma unroll
    for (int j = 0; j < 8; j++) {
      int n = n0 + tc * 8 + j;
      float bv = bias[n];
#pragma unroll
      for (int i = 0; i < 8; i += 4) {
        float4 v;
        v.x = acc[i + 0][j] + bv;
        v.y = acc[i + 1][j] + bv;
        v.z = acc[i + 2][j] + bv;
        v.w = acc[i + 3][j] + bv;
        *(float4*)&C[(size_t)n * ldc + m0 + tr * 8 + i] = v;
      }
    }
  }
}

// ------------------------- persistent LSTM recurrence ------------------------
__device__ __forceinline__ void gridbar() {
  __threadfence();
  __syncthreads();
  if (threadIdx.x == 0) {
    unsigned e = *(volatile unsigned*)&g_epoch;
    __threadfence();
    unsigned prev = atomicAdd(&g_count, 1u);
    if (prev == (unsigned)(LSTM_GRID - 1)) {
      atomicExch(&g_count, 0u);
      __threadfence();
      atomicAdd(&g_epoch, 1u);
    } else {
      while (*(volatile unsigned*)&g_epoch == e) __nanosleep(64);
    }
    __threadfence();
  }
  __syncthreads();
}

__device__ __forceinline__ void stage_h(float* h_sm, const float* __restrict__ src) {
  for (int i = threadIdx.x; i < 4096; i += 256) {
    int b = i >> 7;
    int k4 = (i & 127) << 2;
    float4 v = *(const float4*)(src + b * 512 + k4);
    *(float4*)(h_sm + b * HS + k4) = v;
  }
}

__device__ __forceinline__ void accum512(const float* __restrict__ Wr0,
                                         const float* __restrict__ Wr1,
                                         const float* __restrict__ hrow,
                                         float& acc0, float& acc1) {
#pragma unroll 4
  for (int k = 0; k < 512; k += 4) {
    float4 hv = *(const float4*)(hrow + k);
    float4 w0 = *(const float4*)(Wr0 + k);
    float4 w1 = *(const float4*)(Wr1 + k);
    acc0 += w0.x * hv.x; acc1 += w1.x * hv.x;
    acc0 += w0.y * hv.y; acc1 += w1.y * hv.y;
    acc0 += w0.z * hv.z; acc1 += w1.z * hv.z;
    acc0 += w0.w * hv.w; acc1 += w1.w * hv.w;
  }
}

__device__ __forceinline__ float sigm(float x) { return 1.f / (1.f + __expf(-x)); }

__global__ void __launch_bounds__(256, 1)
lstm_kernel(const float* __restrict__ fcW, const float* __restrict__ fcb,
            float* __restrict__ out) {
  extern __shared__ float sm[];
  float* W0s = sm + OFF_W0;
  float* W1s = sm + OFF_W1;
  float* h_sm = sm + OFF_H;
  float* a_sm = sm + OFF_A;
  float* b1s = sm + OFF_B1;

  const int tid = threadIdx.x;
  const int w = tid >> 5;
  const int lane = tid & 31;
  const int cta = blockIdx.x;

  for (int i = tid; i < 16 * 512; i += 256) {
    int r = i >> 9, k = i & 511;
    int gr = cta * 4 + (r >> 2) + (r & 3) * 512;
    W0s[i] = fcW[(size_t)gr * 1024 + 512 + k];
  }
  for (int i = tid; i < 16 * 1024; i += 256) {
    int r = i >> 10, k = i & 1023;
    int gr = cta * 4 + (r >> 2) + (r & 3) * 512;
    W1s[i] = fcW[(size_t)2048 * 1024 + (size_t)gr * 1024 + k];
  }
  if (tid < 16)
    b1s[tid] = fcb[2048 + cta * 4 + (tid >> 2) + (tid & 3) * 512];

  {
    int g = cta * 256 + tid;
    if (g < BATCH * NHID) {
      g_h0[0][g] = 0.f; g_h0[1][g] = 0.f;
      g_h1[0][g] = 0.f; g_h1[1][g] = 0.f;
    }
  }
  gridbar();

  float c0r = 0.f, c1r = 0.f;
  const int U = cta * 4 + (w & 3);
  float* hid = out + HID_OFF;

  for (int t = 0; t < SEQ; ++t) {
    const int p = t & 1;
    const int m = t * 32 + lane;

    stage_h(h_sm, &g_h0[p][0]);
    __syncthreads();
    {
      float a0 = 0.f, a1 = 0.f;
      accum512(W0s + (2 * w) * 512, W0s + (2 * w + 1) * 512,
               h_sm + lane * HS, a0, a1);
      a_sm[(2 * w) * 32 + lane] = a0;
      a_sm[(2 * w + 1) * 32 + lane] = a1;
    }
    __syncthreads();
    if (w < 4) {
      float a[4];
#pragma unroll
      for (int g = 0; g < 4; ++g)
        a[g] = a_sm[(w * 4 + g) * 32 + lane] +
               g_g0xT[(size_t)(U + g * 512) * M_ROWS + m];
      float ig = sigm(a[0]), fg = sigm(a[1]), og = sigm(a[2]);
      float bg = tanhf(a[3]);
      c0r = fg * c0r + ig * bg;
      float h0v = og * tanhf(c0r);
      g_h0[p ^ 1][lane * 512 + U] = h0v;
      if (t == SEQ - 1) hid[lane * 512 + U] = h0v;
    }
    gridbar();

    stage_h(h_sm, &g_h0[p ^ 1][0]);
    __syncthreads();
    float a0 = 0.f, a1 = 0.f;
    accum512(W1s + (2 * w) * 1024, W1s + (2 * w + 1) * 1024,
             h_sm + lane * HS, a0, a1);
    __syncthreads();
    stage_h(h_sm, &g_h1[p][0]);
    __syncthreads();
    accum512(W1s + (2 * w) * 1024 + 512, W1s + (2 * w + 1) * 1024 + 512,
             h_sm + lane * HS, a0, a1);
    a_sm[(2 * w) * 32 + lane] = a0;
    a_sm[(2 * w + 1) * 32 + lane] = a1;
    __syncthreads();
    if (w < 4) {
      float a[4];
#pragma unroll
      for (int g = 0; g < 4; ++g)
        a[g] = a_sm[(w * 4 + g) * 32 + lane] + b1s[w * 4 + g];
      float ig = sigm(a[0]), fg = sigm(a[1]), og = sigm(a[2]);
      float bg = tanhf(a[3]);
      c1r = fg * c1r + ig * bg;
      float h1v = og * tanhf(c1r);
      g_h1[p ^ 1][lane * 512 + U] = h1v;
      g_outT[(size_t)U * M_ROWS + m] = h1v;
      if (t == SEQ - 1) hid[16384 + lane * 512 + U] = h1v;
    }
    gridbar();
  }
}

// ------------------------- bf16 split conversions ----------------------------
__global__ void convB_kernel(const float* __restrict__ W) {
  int i = blockIdx.x * 256 + threadIdx.x;
  if (i >= NVOC * NHID) return;
  float x = W[i];
  __nv_bfloat16 h = __float2bfloat16(x);
  g_Bhi[i] = h;
  g_Blo[i] = __float2bfloat16(x - __bfloat162float(h));
}

// transpose g_outT [k][m] -> row-major A[m][k] split into hi/lo bf16
__global__ void convA_kernel() {
  __shared__ float t[32][33];
  int kb = blockIdx.x, mb = blockIdx.y;
  int x = threadIdx.x, y = threadIdx.y;  // 32 x 8
  for (int yy = y; yy < 32; yy += 8)
    t[yy][x] = g_outT[(size_t)(kb * 32 + yy) * M_ROWS + mb * 32 + x];
  __syncthreads();
  for (int yy = y; yy < 32; yy += 8) {
    float v = t[x][yy];
    size_t o = (size_t)(mb * 32 + yy) * NHID + kb * 32 + x;
    __nv_bfloat16 h = __float2bfloat16(v);
    g_Ahi[o] = h;
    g_Alo[o] = __float2bfloat16(v - __bfloat162float(h));
  }
}

// ------------------------- HMMA (mma.sync) decoder GEMM ----------------------
// C[4096,32000] = Ahi*Bhi^T + Ahi*Blo^T + Alo*Bhi^T + bias  (split-bf16 fp32)
// Tile 128x128 per CTA, 8 warps (2x4), warp tile 64x32, BK=32 double-buffered.
#define DEC_BM 128
#define DEC_BN 128
#define DEC_BK 32
#define DEC_LDS 40                         /* padded smem row stride (bf16) */
#define TSZ (128 * DEC_LDS * 2)            /* bytes per matrix per stage */
#define SO_BIAS 0                          /* 128 floats = 512 B */
#define SO_AH 512
#define SO_AL (512 + 2 * TSZ)
#define SO_BH (512 + 4 * TSZ)
#define SO_BL (512 + 6 * TSZ)
#define DEC_SMEM (512 + 8 * TSZ)           /* 82432 B */

__device__ __forceinline__ uint32_t smem_u32(const void* p) {
  uint32_t a;
  asm("{ .reg .u64 t; cvta.to.shared.u64 t, %1; cvt.u32.u64 %0, t; }"
      : "=r"(a) : "l"(p));
  return a;
}
__device__ __forceinline__ void cp16(uint32_t dst, const void* src) {
  asm volatile("cp.async.cg.shared.global [%0], [%1], 16;\n" ::"r"(dst), "l"(src));
}
__device__ __forceinline__ void ldm_x4(uint32_t a, uint32_t* r) {
  asm volatile("ldmatrix.sync.aligned.m8n8.x4.shared.b16 {%0,%1,%2,%3}, [%4];"
               : "=r"(r[0]), "=r"(r[1]), "=r"(r[2]), "=r"(r[3]) : "r"(a));
}
__device__ __forceinline__ void ldm_x2(uint32_t a, uint32_t* r) {
  asm volatile("ldmatrix.sync.aligned.m8n8.x2.shared.b16 {%0,%1}, [%2];"
               : "=r"(r[0]), "=r"(r[1]) : "r"(a));
}
__device__ __forceinline__ void mma16816(float* c, const uint32_t* a,
                                         const uint32_t* b) {
  asm volatile(
      "mma.sync.aligned.m16n8k16.row.col.f32.bf16.bf16.f32 "
      "{%0,%1,%2,%3}, {%4,%5,%6,%7}, {%8,%9}, {%0,%1,%2,%3};"
      : "+f"(c[0]), "+f"(c[1]), "+f"(c[2]), "+f"(c[3])
      : "r"(a[0]), "r"(a[1]), "r"(a[2]), "r"(a[3]), "r"(b[0]), "r"(b[1]));
}

__device__ __forceinline__ void dec_load(uint32_t sb, int s, int kt,
                                         int m0, int n0, int tid) {
  const int k0 = kt * DEC_BK;
  const uint32_t so = (uint32_t)s * TSZ;
#pragma unroll
  for (int i = tid; i < 512; i += 256) {
    int row = i >> 2, c = (i & 3) * 8;
    uint32_t doff = so + (uint32_t)(row * DEC_LDS + c) * 2;
    cp16(sb + SO_AH + doff, g_Ahi + (size_t)(m0 + row) * NHID + k0 + c);
    cp16(sb + SO_AL + doff, g_Alo + (size_t)(m0 + row) * NHID + k0 + c);
    cp16(sb + SO_BH + doff, g_Bhi + (size_t)(n0 + row) * NHID + k0 + c);
    cp16(sb + SO_BL + doff, g_Blo + (size_t)(n0 + row) * NHID + k0 + c);
  }
  asm volatile("cp.async.commit_group;\n" ::: "memory");
}

__global__ void __launch_bounds__(256, 1)
dec_mma_kernel(const float* __restrict__ bias, float* __restrict__ C) {
  extern __shared__ char smem[];
  uint32_t sb = smem_u32(smem);
  const int tid = threadIdx.x;
  const int wid = tid >> 5;
  const int lane = tid & 31;
  const int m0 = blockIdx.x * DEC_BM;
  const int n0 = blockIdx.y * DEC_BN;
  const int wm = (wid >> 2) * 64;   // warp m offset in tile
  const int wn = (wid & 3) * 32;    // warp n offset in tile

  if (tid < 128) ((float*)(smem + SO_BIAS))[tid] = bias[n0 + tid];

  float acc[4][4][4];
#pragma unroll
  for (int i = 0; i < 4; i++)
#pragma unroll
    for (int j = 0; j < 4; j++)
#pragma unroll
      for (int v = 0; v < 4; v++) acc[i][j][v] = 0.f;

  dec_load(sb, 0, 0, m0, n0, tid);
  dec_load(sb, 1, 1, m0, n0, tid);

  // per-lane ldmatrix source coordinates
  const int arow = lane & 15, achk = (lane >> 4) * 8;      // A: x4
  const int brow = lane & 7, bchk = ((lane >> 3) & 1) * 8; // B: x2

#pragma unroll 1
  for (int kt = 0; kt < 16; ++kt) {
    asm volatile("cp.async.wait_group 1;\n" ::: "memory");
    __syncthreads();
    const uint32_t so = (uint32_t)(kt & 1) * TSZ;

#pragma unroll
    for (int ks = 0; ks < 2; ++ks) {
      const int kk = ks * 16;
      uint32_t ah[4][4], al[4][4], bh[4][2], bl[4][2];
#pragma unroll
      for (int mf = 0; mf < 4; ++mf) {
        uint32_t off = so + (uint32_t)((wm + mf * 16 + arow) * DEC_LDS + kk + achk) * 2;
        ldm_x4(sb + SO_AH + off, ah[mf]);
        ldm_x4(sb + SO_AL + off, al[mf]);
      }
#pragma unroll
      for (int nf = 0; nf < 4; ++nf) {
        uint32_t off = so + (uint32_t)((wn + nf * 8 + brow) * DEC_LDS + kk + bchk) * 2;
        ldm_x2(sb + SO_BH + off, bh[nf]);
        ldm_x2(sb + SO_BL + off, bl[nf]);
      }
#pragma unroll
      for (int mf = 0; mf < 4; ++mf)
#pragma unroll
        for (int nf = 0; nf < 4; ++nf) {
          mma16816(acc[mf][nf], ah[mf], bh[nf]);
          mma16816(acc[mf][nf], ah[mf], bl[nf]);
          mma16816(acc[mf][nf], al[mf], bh[nf]);
        }
    }
    __syncthreads();
    if (kt + 2 < 16) dec_load(sb, kt & 1, kt + 2, m0, n0, tid);
  }

  // epilogue: C layout per mma frag: c0/c1 at (row, col..col+1), c2/c3 at row+8
  const float* bsm = (const float*)(smem + SO_BIAS);
  const int rl = lane >> 2, cl = (lane & 3) * 2;
#pragma unroll
  for (int mf = 0; mf < 4; ++mf) {
    int r = m0 + wm + mf * 16 + rl;
#pragma unroll
    for (int nf = 0; nf < 4; ++nf) {
      int ci = wn + nf * 8 + cl;
      float b0 = bsm[ci], b1 = bsm[ci + 1];
      float2 v0 = make_float2(acc[mf][nf][0] + b0, acc[mf][nf][1] + b1);
      float2 v1 = make_float2(acc[mf][nf][2] + b0, acc[mf][nf][3] + b1);
      *(float2*)(C + (size_t)r * NVOC + n0 + ci) = v0;
      *(float2*)(C + (size_t)(r + 8) * NVOC + n0 + ci) = v1;
    }
  }
}

// ------------------------- launch ------------------------------------------
extern "C" void kernel_launch(void* const* d_in, const int* in_sizes, int n_in,
                              void* d_out, int out_size) {
  const int* tok = (const int*)d_in[0];
  const float* embW = (const float*)d_in[1];
  const float* fcW = (const float*)d_in[2];
  const float* fcb = (const float*)d_in[3];
  const float* decW = (const float*)d_in[4];
  const float* decb = (const float*)d_in[5];
  float* out = (float*)d_out;

  void *p_embT = 0, *p_g0xT = 0;
  cudaGetSymbolAddress(&p_embT, g_embT);
  cudaGetSymbolAddress(&p_g0xT, g_g0xT);

  // 1) embedding gather -> embT
  embed_kernel<<<(NHID * M_ROWS + 255) / 256, 256>>>(tok, embW);

  // 2) decoder weight split to bf16 (independent of recurrence)
  convB_kernel<<<(NVOC * NHID + 255) / 256, 256>>>(decW);

  // 3) layer-0 input projection for all timesteps: g0xT[g][m]
  sgemm_atn<true><<<dim3(M_ROWS / 128, 2048 / 128), 256>>>(
      (const float*)p_embT, fcW, 1024, fcb,
      (float*)p_g0xT, M_ROWS, M_ROWS, 2048, NHID);

  // 4) persistent LSTM recurrence
  cudaFuncSetAttribute(lstm_kernel,
                       cudaFuncAttributeMaxDynamicSharedMemorySize, SMEM_BYTES);
  lstm_kernel<<<LSTM_GRID, 256, SMEM_BYTES>>>(fcW, fcb, out);

  // 5) transpose + split h1 activations to bf16
  convA_kernel<<<dim3(NHID / 32, M_ROWS / 32), dim3(32, 8)>>>();

  // 6) HMMA decoder GEMM
  cudaFuncSetAttribute(dec_mma_kernel,
                       cudaFuncAttributeMaxDynamicSharedMemorySize, DEC_SMEM);
  dec_mma_kernel<<<dim3(M_ROWS / DEC_BM, NVOC / DEC_BN), 256, DEC_SMEM>>>(decb, out);
}

// round 8
// speedup vs baseline: 2.1478x; 1.6342x over previous
#include <cuda_runtime.h>
#include <cuda_bf16.h>
#include <math.h>
#include <stdint.h>

#define SEQ 128
#define BATCH 32
#define NHID 512
#define NVOC 32000
#define M_ROWS (SEQ * BATCH)                 /* 4096 */
#define HID_OFF ((size_t)M_ROWS * NVOC)      /* 131072000 */
#define LSTM_GRID 128

// ------------------------- device scratch (no allocs allowed) ----------------
__device__ float g_embT[(size_t)NHID * M_ROWS];       // emb^T  [512][4096]
__device__ float g_g0xT[(size_t)4 * NHID * M_ROWS];   // layer0 x-gates^T [2048][4096]
__device__ float g_outT[(size_t)NHID * M_ROWS];       // h1 out^T [512][4096]
__device__ float g_h0[2][BATCH * NHID];
__device__ float g_h1[2][BATCH * NHID];
__device__ unsigned g_count = 0;
__device__ unsigned g_epoch = 0;

// split-bf16 operands for the tensor-core decoder
__device__ __nv_bfloat16 g_Ahi[(size_t)M_ROWS * NHID];
__device__ __nv_bfloat16 g_Alo[(size_t)M_ROWS * NHID];
__device__ __nv_bfloat16 g_Bhi[(size_t)NVOC * NHID];
__device__ __nv_bfloat16 g_Blo[(size_t)NVOC * NHID];

// ------------------------- shared PTX helpers --------------------------------
__device__ __forceinline__ uint32_t smem_u32(const void* p) {
  uint32_t a;
  asm("{ .reg .u64 t; cvta.to.shared.u64 t, %1; cvt.u32.u64 %0, t; }"
      : "=r"(a) : "l"(p));
  return a;
}
__device__ __forceinline__ void cp16(uint32_t dst, const void* src) {
  asm volatile("cp.async.cg.shared.global [%0], [%1], 16;\n" ::"r"(dst), "l"(src));
}
__device__ __forceinline__ void ldm_x4(uint32_t a, uint32_t* r) {
  asm volatile("ldmatrix.sync.aligned.m8n8.x4.shared.b16 {%0,%1,%2,%3}, [%4];"
               : "=r"(r[0]), "=r"(r[1]), "=r"(r[2]), "=r"(r[3]) : "r"(a));
}
__device__ __forceinline__ void ldm_x2(uint32_t a, uint32_t* r) {
  asm volatile("ldmatrix.sync.aligned.m8n8.x2.shared.b16 {%0,%1}, [%2];"
               : "=r"(r[0]), "=r"(r[1]) : "r"(a));
}
__device__ __forceinline__ void mma16816(float* c, const uint32_t* a,
                                         const uint32_t* b) {
  asm volatile(
      "mma.sync.aligned.m16n8k16.row.col.f32.bf16.bf16.f32 "
      "{%0,%1,%2,%3}, {%4,%5,%6,%7}, {%8,%9}, {%0,%1,%2,%3};"
      : "+f"(c[0]), "+f"(c[1]), "+f"(c[2]), "+f"(c[3])
      : "r"(a[0]), "r"(a[1]), "r"(a[2]), "r"(a[3]), "r"(b[0]), "r"(b[1]));
}

// ------------------------- embedding gather ----------------------------------
__global__ void embed_kernel(const int* __restrict__ tok,
                             const float* __restrict__ embW) {
  int idx = blockIdx.x * 256 + threadIdx.x;
  if (idx >= NHID * M_ROWS) return;
  int m = idx & (M_ROWS - 1);
  int k = idx >> 12;
  g_embT[idx] = embW[(size_t)tok[m] * NHID + k];
}

// ------------------------- SGEMM (gemm0 only): C^T = A*B^T + bias ------------
template <bool TRANSC>
__global__ void __launch_bounds__(256, 1)
sgemm_atn(const float* __restrict__ AT, const float* __restrict__ B, int ldb,
          const float* __restrict__ bias, float* __restrict__ C, int ldc,
          int M, int N, int K) {
  __shared__ float As[16][128];
  __shared__ float Bs[16][128];
  const int m0 = blockIdx.x * 128, n0 = blockIdx.y * 128;
  const int tid = threadIdx.x;
  const int tr = tid >> 4, tc = tid & 15;

  float acc[8][8];
#pragma unroll
  for (int i = 0; i < 8; i++)
#pragma unroll
    for (int j = 0; j < 8; j++) acc[i][j] = 0.f;

  const int ka = tid >> 5;
  const int ma = (tid & 31) << 2;
  const int nb = tid >> 1;
  const int kb = (tid & 1) << 3;

  for (int k0 = 0; k0 < K; k0 += 16) {
    float4 a0 = *(const float4*)&AT[(size_t)(k0 + ka) * M + m0 + ma];
    float4 a1 = *(const float4*)&AT[(size_t)(k0 + ka + 8) * M + m0 + ma];
    float4 b0 = *(const float4*)&B[(size_t)(n0 + nb) * ldb + k0 + kb];
    float4 b1 = *(const float4*)&B[(size_t)(n0 + nb) * ldb + k0 + kb + 4];
    __syncthreads();
    *(float4*)&As[ka][ma] = a0;
    *(float4*)&As[ka + 8][ma] = a1;
    Bs[kb + 0][nb] = b0.x; Bs[kb + 1][nb] = b0.y;
    Bs[kb + 2][nb] = b0.z; Bs[kb + 3][nb] = b0.w;
    Bs[kb + 4][nb] = b1.x; Bs[kb + 5][nb] = b1.y;
    Bs[kb + 6][nb] = b1.z; Bs[kb + 7][nb] = b1.w;
    __syncthreads();
#pragma unroll
    for (int kk = 0; kk < 16; ++kk) {
      float a[8], bq[8];
      *(float4*)&a[0] = *(const float4*)&As[kk][tr * 8];
      *(float4*)&a[4] = *(const float4*)&As[kk][tr * 8 + 4];
      *(float4*)&bq[0] = *(const float4*)&Bs[kk][tc * 8];
      *(float4*)&bq[4] = *(const float4*)&Bs[kk][tc * 8 + 4];
#pragma unroll
      for (int i = 0; i < 8; i++)
#pragma unroll
        for (int j = 0; j < 8; j++) acc[i][j] += a[i] * bq[j];
    }
  }

  if (!TRANSC) {
#pragma unroll
    for (int i = 0; i < 8; i++) {
      int m = m0 + tr * 8 + i;
#pragma unroll
      for (int j = 0; j < 8; j += 4) {
        int n = n0 + tc * 8 + j;
        float4 v;
        v.x = acc[i][j + 0] + bias[n + 0];
        v.y = acc[i][j + 1] + bias[n + 1];
        v.z = acc[i][j + 2] + bias[n + 2];
        v.w = acc[i][j + 3] + bias[n + 3];
        *(float4*)&C[(size_t)m * ldc + n] = v;
      }
    }
  } else {
#pragma unroll
    for (int j = 0; j < 8; j++) {
      int n = n0 + tc * 8 + j;
      float bv = bias[n];
#pragma unroll
      for (int i = 0; i < 8; i += 4) {
        float4 v;
        v.x = acc[i + 0][j] + bv;
        v.y = acc[i + 1][j] + bv;
        v.z = acc[i + 2][j] + bv;
        v.w = acc[i + 3][j] + bv;
        *(float4*)&C[(size_t)n * ldc + m0 + tr * 8 + i] = v;
      }
    }
  }
}

// ------------------------- HMMA persistent LSTM ------------------------------
// smem byte offsets (strides chosen for conflict-free ldmatrix: stride/2 %32 == 4)
#define LW0 520   /* W0 row stride, bf16 elems (16 rows, K=512) */
#define LW1 1032  /* W1 row stride, bf16 elems (16 rows, K=1024) */
#define LH  520   /* h staging row stride (32 rows, K=512) */
#define SO_W0HI 0
#define SO_W0LO 16640
#define SO_W1HI 33280
#define SO_W1LO 66304
#define SO_HHI  99328
#define SO_HLO  132608
#define SO_PS   165888                 /* 8*32*32 f32 = 32768 */
#define SO_ASM  198656                 /* 32*32 f32 = 4096 */
#define SO_B1S  202752                 /* 16 f32 */
#define LSTM_SMEM 202816

__device__ __forceinline__ void gridbar() {
  __threadfence();
  __syncthreads();
  if (threadIdx.x == 0) {
    unsigned e = *(volatile unsigned*)&g_epoch;
    __threadfence();
    unsigned prev = atomicAdd(&g_count, 1u);
    if (prev == (unsigned)(LSTM_GRID - 1)) {
      atomicExch(&g_count, 0u);
      __threadfence();
      atomicAdd(&g_epoch, 1u);
    } else {
      while (*(volatile unsigned*)&g_epoch == e) __nanosleep(64);
    }
    __threadfence();
  }
  __syncthreads();
}

// stage fp32 h [32][512] -> split bf16 hi/lo smem [32][LH]
__device__ __forceinline__ void stage_split(char* smem, const float* __restrict__ src) {
  __nv_bfloat16* Hhi = (__nv_bfloat16*)(smem + SO_HHI);
  __nv_bfloat16* Hlo = (__nv_bfloat16*)(smem + SO_HLO);
  for (int i = threadIdx.x; i < 4096; i += 256) {
    int b = i >> 7;
    int k4 = (i & 127) << 2;
    float4 v = *(const float4*)(src + b * 512 + k4);
    __nv_bfloat162 h0, h1, l0, l1;
    h0.x = __float2bfloat16(v.x); l0.x = __float2bfloat16(v.x - __bfloat162float(h0.x));
    h0.y = __float2bfloat16(v.y); l0.y = __float2bfloat16(v.y - __bfloat162float(h0.y));
    h1.x = __float2bfloat16(v.z); l1.x = __float2bfloat16(v.z - __bfloat162float(h1.x));
    h1.y = __float2bfloat16(v.w); l1.y = __float2bfloat16(v.w - __bfloat162float(h1.y));
    *(__nv_bfloat162*)(Hhi + b * LH + k4) = h0;
    *(__nv_bfloat162*)(Hhi + b * LH + k4 + 2) = h1;
    *(__nv_bfloat162*)(Hlo + b * LH + k4) = l0;
    *(__nv_bfloat162*)(Hlo + b * LH + k4 + 2) = l1;
  }
}

__device__ __forceinline__ float sigm(float x) { return 1.f / (1.f + __expf(-x)); }

__global__ void __launch_bounds__(256, 1)
lstm_kernel(const float* __restrict__ fcW, const float* __restrict__ fcb,
            float* __restrict__ out) {
  extern __shared__ char smem[];
  uint32_t sb = smem_u32(smem);
  __nv_bfloat16* W0hi = (__nv_bfloat16*)(smem + SO_W0HI);
  __nv_bfloat16* W0lo = (__nv_bfloat16*)(smem + SO_W0LO);
  __nv_bfloat16* W1hi = (__nv_bfloat16*)(smem + SO_W1HI);
  __nv_bfloat16* W1lo = (__nv_bfloat16*)(smem + SO_W1LO);
  float* ps = (float*)(smem + SO_PS);
  float* a_sm = (float*)(smem + SO_ASM);
  float* b1s = (float*)(smem + SO_B1S);

  const int tid = threadIdx.x;
  const int w = tid >> 5;
  const int lane = tid & 31;
  const int cta = blockIdx.x;

  // ---- load + split weight slices into smem (once) ----
  // local row r: unit j=r>>2, gate gg=r&3 -> global gate row gr = cta*4 + j + gg*512
  for (int i = tid; i < 16 * 512; i += 256) {
    int r = i >> 9, k = i & 511;
    int gr = cta * 4 + (r >> 2) + (r & 3) * 512;
    float v = fcW[(size_t)gr * 1024 + 512 + k];           // layer0 h-part
    __nv_bfloat16 h = __float2bfloat16(v);
    W0hi[r * LW0 + k] = h;
    W0lo[r * LW0 + k] = __float2bfloat16(v - __bfloat162float(h));
  }
  for (int i = tid; i < 16 * 1024; i += 256) {
    int r = i >> 10, k = i & 1023;
    int gr = cta * 4 + (r >> 2) + (r & 3) * 512;
    float v = fcW[(size_t)2048 * 1024 + (size_t)gr * 1024 + k];  // layer1 full
    __nv_bfloat16 h = __float2bfloat16(v);
    W1hi[r * LW1 + k] = h;
    W1lo[r * LW1 + k] = __float2bfloat16(v - __bfloat162float(h));
  }
  if (tid < 16)
    b1s[tid] = fcb[2048 + cta * 4 + (tid >> 2) + (tid & 3) * 512];

  // ---- zero initial hidden state (both parities, both layers) ----
  {
    int g = cta * 256 + tid;
    if (g < BATCH * NHID) {
      g_h0[0][g] = 0.f; g_h0[1][g] = 0.f;
      g_h1[0][g] = 0.f; g_h1[1][g] = 0.f;
    }
  }
  gridbar();

  float c0r = 0.f, c1r = 0.f;  // warp 0..3: c0 of unit cta*4+w; warp 4..7: c1
  const int U = cta * 4 + (w & 3);
  float* hid = out + HID_OFF;

  const int arow = lane & 15, achk = (lane >> 4) * 8;
  const int brow = lane & 7, bchk = ((lane >> 3) & 1) * 8;
  const int rl = lane >> 2, cl = (lane & 3) * 2;

  // phase p: layer0 at t=p (p<128), layer1 at t=p-1 (p>=1). 129 phases.
#pragma unroll 1
  for (int p = 0; p <= SEQ; ++p) {
    const int wp = p & 1;

    // prefetch layer0 x-gates (hidden behind staging + mma)
    float xg[4] = {0.f, 0.f, 0.f, 0.f};
    if (w < 4 && p < SEQ) {
#pragma unroll
      for (int g = 0; g < 4; ++g)
        xg[g] = g_g0xT[(size_t)(U + g * 512) * M_ROWS + p * 32 + lane];
    }

    float acc0[2][2][4], acc1[2][2][4];
#pragma unroll
    for (int i = 0; i < 2; i++)
#pragma unroll
      for (int j = 0; j < 2; j++)
#pragma unroll
        for (int v = 0; v < 4; v++) { acc0[i][j][v] = 0.f; acc1[i][j][v] = 0.f; }

    // ---- part 1: stage h0(p-1); mma L0 gates + L1 chunk0 (shared A frags) ----
    stage_split(smem, &g_h0[wp ^ 1][0]);
    __syncthreads();
#pragma unroll
    for (int kt = 0; kt < 4; ++kt) {
      const int kk = (w * 4 + kt) * 16;
      uint32_t ah[2][4], al[2][4], b0h[2][2], b0l[2][2], b1h[2][2], b1l[2][2];
#pragma unroll
      for (int mf = 0; mf < 2; ++mf) {
        uint32_t off = (uint32_t)((mf * 16 + arow) * LH + kk + achk) * 2;
        ldm_x4(sb + SO_HHI + off, ah[mf]);
        ldm_x4(sb + SO_HLO + off, al[mf]);
      }
#pragma unroll
      for (int nf = 0; nf < 2; ++nf) {
        uint32_t o0 = (uint32_t)((nf * 8 + brow) * LW0 + kk + bchk) * 2;
        ldm_x2(sb + SO_W0HI + o0, b0h[nf]);
        ldm_x2(sb + SO_W0LO + o0, b0l[nf]);
        uint32_t o1 = (uint32_t)((nf * 8 + brow) * LW1 + kk + bchk) * 2;
        ldm_x2(sb + SO_W1HI + o1, b1h[nf]);
        ldm_x2(sb + SO_W1LO + o1, b1l[nf]);
      }
#pragma unroll
      for (int mf = 0; mf < 2; ++mf)
#pragma unroll
        for (int nf = 0; nf < 2; ++nf) {
          mma16816(acc0[mf][nf], ah[mf], b0h[nf]);
          mma16816(acc0[mf][nf], ah[mf], b0l[nf]);
          mma16816(acc0[mf][nf], al[mf], b0h[nf]);
          mma16816(acc1[mf][nf], ah[mf], b1h[nf]);
          mma16816(acc1[mf][nf], ah[mf], b1l[nf]);
          mma16816(acc1[mf][nf], al[mf], b1h[nf]);
        }
    }
    __syncthreads();

    // ---- part 2: stage h1(p-2); mma L1 chunk1 ----
    stage_split(smem, &g_h1[wp ^ 1][0]);
    __syncthreads();
#pragma unroll
    for (int kt = 0; kt < 4; ++kt) {
      const int kk = (w * 4 + kt) * 16;
      uint32_t ah[2][4], al[2][4], b1h[2][2], b1l[2][2];
#pragma unroll
      for (int mf = 0; mf < 2; ++mf) {
        uint32_t off = (uint32_t)((mf * 16 + arow) * LH + kk + achk) * 2;
        ldm_x4(sb + SO_HHI + off, ah[mf]);
        ldm_x4(sb + SO_HLO + off, al[mf]);
      }
#pragma unroll
      for (int nf = 0; nf < 2; ++nf) {
        uint32_t o1 = (uint32_t)((nf * 8 + brow) * LW1 + 512 + kk + bchk) * 2;
        ldm_x2(sb + SO_W1HI + o1, b1h[nf]);
        ldm_x2(sb + SO_W1LO + o1, b1l[nf]);
      }
#pragma unroll
      for (int mf = 0; mf < 2; ++mf)
#pragma unroll
        for (int nf = 0; nf < 2; ++nf) {
          mma16816(acc1[mf][nf], ah[mf], b1h[nf]);
          mma16816(acc1[mf][nf], ah[mf], b1l[nf]);
          mma16816(acc1[mf][nf], al[mf], b1h[nf]);
        }
    }

    // ---- store partials: ps[warp][n][b], n<16 = L0, n>=16 = L1 ----
#pragma unroll
    for (int mf = 0; mf < 2; ++mf)
#pragma unroll
      for (int nf = 0; nf < 2; ++nf)
#pragma unroll
        for (int v = 0; v < 4; ++v) {
          int b = mf * 16 + rl + ((v & 2) ? 8 : 0);
          int n = nf * 8 + cl + (v & 1);
          ps[(w * 32 + n) * 32 + b] = acc0[mf][nf][v];
          ps[(w * 32 + 16 + n) * 32 + b] = acc1[mf][nf][v];
        }
    __syncthreads();

    // ---- reduce 8 partials -> a_sm[n][b] ----
#pragma unroll
    for (int q = 0; q < 4; ++q) {
      int o = tid + q * 256;
      int n = o >> 5, b = o & 31;
      float s = 0.f;
#pragma unroll
      for (int ww = 0; ww < 8; ++ww) s += ps[(ww * 32 + n) * 32 + b];
      a_sm[n * 32 + b] = s;
    }
    __syncthreads();

    // ---- activations + state update ----
    if (w < 4) {
      if (p < SEQ) {
        float a[4];
#pragma unroll
        for (int g = 0; g < 4; ++g)
          a[g] = a_sm[(w * 4 + g) * 32 + lane] + xg[g];
        float ig = sigm(a[0]), fg = sigm(a[1]), og = sigm(a[2]);
        float bg = tanhf(a[3]);
        c0r = fg * c0r + ig * bg;
        float h0v = og * tanhf(c0r);
        g_h0[wp][lane * 512 + U] = h0v;
        if (p == SEQ - 1) hid[lane * 512 + U] = h0v;
      }
    } else {
      if (p >= 1) {
        float a[4];
#pragma unroll
        for (int g = 0; g < 4; ++g)
          a[g] = a_sm[(16 + (w - 4) * 4 + g) * 32 + lane] + b1s[(w - 4) * 4 + g];
        float ig = sigm(a[0]), fg = sigm(a[1]), og = sigm(a[2]);
        float bg = tanhf(a[3]);
        c1r = fg * c1r + ig * bg;
        float h1v = og * tanhf(c1r);
        g_h1[wp][lane * 512 + U] = h1v;
        g_outT[(size_t)U * M_ROWS + (p - 1) * 32 + lane] = h1v;
        if (p == SEQ) hid[16384 + lane * 512 + U] = h1v;
      }
    }
    gridbar();
  }
}

// ------------------------- bf16 split conversions ----------------------------
__global__ void convB_kernel(const float* __restrict__ W) {
  int i = blockIdx.x * 256 + threadIdx.x;
  if (i >= NVOC * NHID) return;
  float x = W[i];
  __nv_bfloat16 h = __float2bfloat16(x);
  g_Bhi[i] = h;
  g_Blo[i] = __float2bfloat16(x - __bfloat162float(h));
}

// transpose g_outT [k][m] -> row-major A[m][k] split into hi/lo bf16
__global__ void convA_kernel() {
  __shared__ float t[32][33];
  int kb = blockIdx.x, mb = blockIdx.y;
  int x = threadIdx.x, y = threadIdx.y;  // 32 x 8
  for (int yy = y; yy < 32; yy += 8)
    t[yy][x] = g_outT[(size_t)(kb * 32 + yy) * M_ROWS + mb * 32 + x];
  __syncthreads();
  for (int yy = y; yy < 32; yy += 8) {
    float v = t[x][yy];
    size_t o = (size_t)(mb * 32 + yy) * NHID + kb * 32 + x;
    __nv_bfloat16 h = __float2bfloat16(v);
    g_Ahi[o] = h;
    g_Alo[o] = __float2bfloat16(v - __bfloat162float(h));
  }
}

// ------------------------- HMMA (mma.sync) decoder GEMM ----------------------
#define DEC_BM 128
#define DEC_BN 128
#define DEC_BK 32
#define DEC_LDS 40
#define TSZ (128 * DEC_LDS * 2)
#define SO_BIAS 0
#define SO_AH 512
#define SO_AL (512 + 2 * TSZ)
#define SO_BH (512 + 4 * TSZ)
#define SO_BL (512 + 6 * TSZ)
#define DEC_SMEM (512 + 8 * TSZ)

__device__ __forceinline__ void dec_load(uint32_t sb, int s, int kt,
                                         int m0, int n0, int tid) {
  const int k0 = kt * DEC_BK;
  const uint32_t so = (uint32_t)s * TSZ;
#pragma unroll
  for (int i = tid; i < 512; i += 256) {
    int row = i >> 2, c = (i & 3) * 8;
    uint32_t doff = so + (uint32_t)(row * DEC_LDS + c) * 2;
    cp16(sb + SO_AH + doff, g_Ahi + (size_t)(m0 + row) * NHID + k0 + c);
    cp16(sb + SO_AL + doff, g_Alo + (size_t)(m0 + row) * NHID + k0 + c);
    cp16(sb + SO_BH + doff, g_Bhi + (size_t)(n0 + row) * NHID + k0 + c);
    cp16(sb + SO_BL + doff, g_Blo + (size_t)(n0 + row) * NHID + k0 + c);
  }
  asm volatile("cp.async.commit_group;\n" ::: "memory");
}

__global__ void __launch_bounds__(256, 1)
dec_mma_kernel(const float* __restrict__ bias, float* __restrict__ C) {
  extern __shared__ char smem[];
  uint32_t sb = smem_u32(smem);
  const int tid = threadIdx.x;
  const int wid = tid >> 5;
  const int lane = tid & 31;
  const int m0 = blockIdx.x * DEC_BM;
  const int n0 = blockIdx.y * DEC_BN;
  const int wm = (wid >> 2) * 64;
  const int wn = (wid & 3) * 32;

  if (tid < 128) ((float*)(smem + SO_BIAS))[tid] = bias[n0 + tid];

  float acc[4][4][4];
#pragma unroll
  for (int i = 0; i < 4; i++)
#pragma unroll
    for (int j = 0; j < 4; j++)
#pragma unroll
      for (int v = 0; v < 4; v++) acc[i][j][v] = 0.f;

  dec_load(sb, 0, 0, m0, n0, tid);
  dec_load(sb, 1, 1, m0, n0, tid);

  const int arow = lane & 15, achk = (lane >> 4) * 8;
  const int brow = lane & 7, bchk = ((lane >> 3) & 1) * 8;

#pragma unroll 1
  for (int kt = 0; kt < 16; ++kt) {
    asm volatile("cp.async.wait_group 1;\n" ::: "memory");
    __syncthreads();
    const uint32_t so = (uint32_t)(kt & 1) * TSZ;

#pragma unroll
    for (int ks = 0; ks < 2; ++ks) {
      const int kk = ks * 16;
      uint32_t ah[4][4], al[4][4], bh[4][2], bl[4][2];
#pragma unroll
      for (int mf = 0; mf < 4; ++mf) {
        uint32_t off = so + (uint32_t)((wm + mf * 16 + arow) * DEC_LDS + kk + achk) * 2;
        ldm_x4(sb + SO_AH + off, ah[mf]);
        ldm_x4(sb + SO_AL + off, al[mf]);
      }
#pragma unroll
      for (int nf = 0; nf < 4; ++nf) {
        uint32_t off = so + (uint32_t)((wn + nf * 8 + brow) * DEC_LDS + kk + bchk) * 2;
        ldm_x2(sb + SO_BH + off, bh[nf]);
        ldm_x2(sb + SO_BL + off, bl[nf]);
      }
#pragma unroll
      for (int mf = 0; mf < 4; ++mf)
#pragma unroll
        for (int nf = 0; nf < 4; ++nf) {
          mma16816(acc[mf][nf], ah[mf], bh[nf]);
          mma16816(acc[mf][nf], ah[mf], bl[nf]);
          mma16816(acc[mf][nf], al[mf], bh[nf]);
        }
    }
    __syncthreads();
    if (kt + 2 < 16) dec_load(sb, kt & 1, kt + 2, m0, n0, tid);
  }

  const float* bsm = (const float*)(smem + SO_BIAS);
  const int rl = lane >> 2, cl = (lane & 3) * 2;
#pragma unroll
  for (int mf = 0; mf < 4; ++mf) {
    int r = m0 + wm + mf * 16 + rl;
#pragma unroll
    for (int nf = 0; nf < 4; ++nf) {
      int ci = wn + nf * 8 + cl;
      float b0 = bsm[ci], b1 = bsm[ci + 1];
      float2 v0 = make_float2(acc[mf][nf][0] + b0, acc[mf][nf][1] + b1);
      float2 v1 = make_float2(acc[mf][nf][2] + b0, acc[mf][nf][3] + b1);
      *(float2*)(C + (size_t)r * NVOC + n0 + ci) = v0;
      *(float2*)(C + (size_t)(r + 8) * NVOC + n0 + ci) = v1;
    }
  }
}

// ------------------------- launch ------------------------------------------
extern "C" void kernel_launch(void* const* d_in, const int* in_sizes, int n_in,
                              void* d_out, int out_size) {
  const int* tok = (const int*)d_in[0];
  const float* embW = (const float*)d_in[1];
  const float* fcW = (const float*)d_in[2];
  const float* fcb = (const float*)d_in[3];
  const float* decW = (const float*)d_in[4];
  const float* decb = (const float*)d_in[5];
  float* out = (float*)d_out;

  void *p_embT = 0, *p_g0xT = 0;
  cudaGetSymbolAddress(&p_embT, g_embT);
  cudaGetSymbolAddress(&p_g0xT, g_g0xT);

  // 1) embedding gather -> embT
  embed_kernel<<<(NHID * M_ROWS + 255) / 256, 256>>>(tok, embW);

  // 2) decoder weight split to bf16
  convB_kernel<<<(NVOC * NHID + 255) / 256, 256>>>(decW);

  // 3) layer-0 input projection for all timesteps: g0xT[g][m]
  sgemm_atn<true><<<dim3(M_ROWS / 128, 2048 / 128), 256>>>(
      (const float*)p_embT, fcW, 1024, fcb,
      (float*)p_g0xT, M_ROWS, M_ROWS, 2048, NHID);

  // 4) persistent HMMA LSTM recurrence
  cudaFuncSetAttribute(lstm_kernel,
                       cudaFuncAttributeMaxDynamicSharedMemorySize, LSTM_SMEM);
  lstm_kernel<<<LSTM_GRID, 256, LSTM_SMEM>>>(fcW, fcb, out);

  // 5) transpose + split h1 activations to bf16
  convA_kernel<<<dim3(NHID / 32, M_ROWS / 32), dim3(32, 8)>>>();

  // 6) HMMA decoder GEMM
  cudaFuncSetAttribute(dec_mma_kernel,
                       cudaFuncAttributeMaxDynamicSharedMemorySize, DEC_SMEM);
  dec_mma_kernel<<<dim3(M_ROWS / DEC_BM, NVOC / DEC_BN), 256, DEC_SMEM>>>(decb, out);
}

// round 9
// speedup vs baseline: 2.4108x; 1.1224x over previous
#include <cuda_runtime.h>
#include <cuda_bf16.h>
#include <math.h>
#include <stdint.h>

#define SEQ 128
#define BATCH 32
#define NHID 512
#define NVOC 32000
#define M_ROWS (SEQ * BATCH)                 /* 4096 */
#define HID_OFF ((size_t)M_ROWS * NVOC)      /* 131072000 */
#define LSTM_GRID 128

// ------------------------- device scratch (no allocs allowed) ----------------
__device__ float g_g0xT[(size_t)4 * NHID * M_ROWS];   // layer0 x-gates^T [2048][4096]
__device__ float g_outT[(size_t)NHID * M_ROWS];       // h1 out^T [512][4096]
__device__ float g_h0[2][BATCH * NHID];
__device__ float g_h1[2][BATCH * NHID];
__device__ unsigned g_count = 0;
__device__ unsigned g_epoch = 0;

// split-bf16 operands
__device__ __nv_bfloat16 g_Ehi[(size_t)M_ROWS * NHID];   // emb  [m][k]
__device__ __nv_bfloat16 g_Elo[(size_t)M_ROWS * NHID];
__device__ __nv_bfloat16 g_W0hi[(size_t)2048 * NHID];    // fcW0 x-part [n][k]
__device__ __nv_bfloat16 g_W0lo[(size_t)2048 * NHID];
__device__ __nv_bfloat16 g_Ahi[(size_t)M_ROWS * NHID];   // h1 out [m][k]
__device__ __nv_bfloat16 g_Alo[(size_t)M_ROWS * NHID];
__device__ __nv_bfloat16 g_Bhi[(size_t)NVOC * NHID];     // decW  [n][k]
__device__ __nv_bfloat16 g_Blo[(size_t)NVOC * NHID];

// ------------------------- shared PTX helpers --------------------------------
__device__ __forceinline__ uint32_t smem_u32(const void* p) {
  uint32_t a;
  asm("{ .reg .u64 t; cvta.to.shared.u64 t, %1; cvt.u32.u64 %0, t; }"
      : "=r"(a) : "l"(p));
  return a;
}
__device__ __forceinline__ void cp16(uint32_t dst, const void* src) {
  asm volatile("cp.async.cg.shared.global [%0], [%1], 16;\n" ::"r"(dst), "l"(src));
}
__device__ __forceinline__ void ldm_x4(uint32_t a, uint32_t* r) {
  asm volatile("ldmatrix.sync.aligned.m8n8.x4.shared.b16 {%0,%1,%2,%3}, [%4];"
               : "=r"(r[0]), "=r"(r[1]), "=r"(r[2]), "=r"(r[3]) : "r"(a));
}
__device__ __forceinline__ void ldm_x2(uint32_t a, uint32_t* r) {
  asm volatile("ldmatrix.sync.aligned.m8n8.x2.shared.b16 {%0,%1}, [%2];"
               : "=r"(r[0]), "=r"(r[1]) : "r"(a));
}
__device__ __forceinline__ void mma16816(float* c, const uint32_t* a,
                                         const uint32_t* b) {
  asm volatile(
      "mma.sync.aligned.m16n8k16.row.col.f32.bf16.bf16.f32 "
      "{%0,%1,%2,%3}, {%4,%5,%6,%7}, {%8,%9}, {%0,%1,%2,%3};"
      : "+f"(c[0]), "+f"(c[1]), "+f"(c[2]), "+f"(c[3])
      : "r"(a[0]), "r"(a[1]), "r"(a[2]), "r"(a[3]), "r"(b[0]), "r"(b[1]));
}

// ------------------------- embedding gather (split bf16, row-major) ----------
__global__ void embed_kernel(const int* __restrict__ tok,
                             const float* __restrict__ embW) {
  int idx = blockIdx.x * 256 + threadIdx.x;
  if (idx >= M_ROWS * NHID) return;
  int m = idx >> 9;
  int k = idx & 511;
  float v = embW[(size_t)tok[m] * NHID + k];
  __nv_bfloat16 h = __float2bfloat16(v);
  g_Ehi[idx] = h;
  g_Elo[idx] = __float2bfloat16(v - __bfloat162float(h));
}

// ------------------------- weight split conversions --------------------------
__global__ void convW0_kernel(const float* __restrict__ fcW) {
  int i = blockIdx.x * 256 + threadIdx.x;
  if (i >= 2048 * NHID) return;
  int n = i >> 9, k = i & 511;
  float x = fcW[(size_t)n * 1024 + k];
  __nv_bfloat16 h = __float2bfloat16(x);
  g_W0hi[i] = h;
  g_W0lo[i] = __float2bfloat16(x - __bfloat162float(h));
}

__global__ void convB_kernel(const float* __restrict__ W) {
  int i = blockIdx.x * 256 + threadIdx.x;
  if (i >= NVOC * NHID) return;
  float x = W[i];
  __nv_bfloat16 h = __float2bfloat16(x);
  g_Bhi[i] = h;
  g_Blo[i] = __float2bfloat16(x - __bfloat162float(h));
}

// transpose g_outT [k][m] -> row-major A[m][k] split into hi/lo bf16
__global__ void convA_kernel() {
  __shared__ float t[32][33];
  int kb = blockIdx.x, mb = blockIdx.y;
  int x = threadIdx.x, y = threadIdx.y;  // 32 x 8
  for (int yy = y; yy < 32; yy += 8)
    t[yy][x] = g_outT[(size_t)(kb * 32 + yy) * M_ROWS + mb * 32 + x];
  __syncthreads();
  for (int yy = y; yy < 32; yy += 8) {
    float v = t[x][yy];
    size_t o = (size_t)(mb * 32 + yy) * NHID + kb * 32 + x;
    __nv_bfloat16 h = __float2bfloat16(v);
    g_Ahi[o] = h;
    g_Alo[o] = __float2bfloat16(v - __bfloat162float(h));
  }
}

// ------------------------- HMMA GEMM (decoder + gemm0) -----------------------
// C = A(split) . B(split)^T + bias ; A[m][512], B[n][512], 3-term split-bf16.
// Tile 128x128, 8 warps (2x4), warp tile 64x32, BK=32 double-buffered, K=512.
#define DEC_LDS 40
#define TSZ (128 * DEC_LDS * 2)
#define SO_BIAS 0
#define SO_AH 512
#define SO_AL (512 + 2 * TSZ)
#define SO_BH (512 + 4 * TSZ)
#define SO_BL (512 + 6 * TSZ)
#define DEC_SMEM (512 + 8 * TSZ)

__device__ __forceinline__ void dec_load(uint32_t sb, int s, int kt,
                                         int m0, int n0, int tid,
                                         const __nv_bfloat16* Ahi,
                                         const __nv_bfloat16* Alo,
                                         const __nv_bfloat16* Bhi,
                                         const __nv_bfloat16* Blo) {
  const int k0 = kt * 32;
  const uint32_t so = (uint32_t)s * TSZ;
#pragma unroll
  for (int i = tid; i < 512; i += 256) {
    int row = i >> 2, c = (i & 3) * 8;
    uint32_t doff = so + (uint32_t)(row * DEC_LDS + c) * 2;
    cp16(sb + SO_AH + doff, Ahi + (size_t)(m0 + row) * NHID + k0 + c);
    cp16(sb + SO_AL + doff, Alo + (size_t)(m0 + row) * NHID + k0 + c);
    cp16(sb + SO_BH + doff, Bhi + (size_t)(n0 + row) * NHID + k0 + c);
    cp16(sb + SO_BL + doff, Blo + (size_t)(n0 + row) * NHID + k0 + c);
  }
  asm volatile("cp.async.commit_group;\n" ::: "memory");
}

template <bool TRANSC>
__global__ void __launch_bounds__(256, 2)
mma_gemm(const __nv_bfloat16* __restrict__ Ahi,
         const __nv_bfloat16* __restrict__ Alo,
         const __nv_bfloat16* __restrict__ Bhi,
         const __nv_bfloat16* __restrict__ Blo,
         const float* __restrict__ bias, float* __restrict__ C, int ldc) {
  extern __shared__ char smem[];
  uint32_t sb = smem_u32(smem);
  const int tid = threadIdx.x;
  const int wid = tid >> 5;
  const int lane = tid & 31;
  const int m0 = blockIdx.x * 128;
  const int n0 = blockIdx.y * 128;
  const int wm = (wid >> 2) * 64;
  const int wn = (wid & 3) * 32;

  if (tid < 128) ((float*)(smem + SO_BIAS))[tid] = bias[n0 + tid];

  float acc[4][4][4];
#pragma unroll
  for (int i = 0; i < 4; i++)
#pragma unroll
    for (int j = 0; j < 4; j++)
#pragma unroll
      for (int v = 0; v < 4; v++) acc[i][j][v] = 0.f;

  dec_load(sb, 0, 0, m0, n0, tid, Ahi, Alo, Bhi, Blo);
  dec_load(sb, 1, 1, m0, n0, tid, Ahi, Alo, Bhi, Blo);

  const int arow = lane & 15, achk = (lane >> 4) * 8;
  const int brow = lane & 7, bchk = ((lane >> 3) & 1) * 8;

#pragma unroll 1
  for (int kt = 0; kt < 16; ++kt) {
    asm volatile("cp.async.wait_group 1;\n" ::: "memory");
    __syncthreads();
    const uint32_t so = (uint32_t)(kt & 1) * TSZ;

#pragma unroll
    for (int ks = 0; ks < 2; ++ks) {
      const int kk = ks * 16;
      uint32_t ah[4][4], al[4][4];
#pragma unroll
      for (int mf = 0; mf < 4; ++mf) {
        uint32_t off = so + (uint32_t)((wm + mf * 16 + arow) * DEC_LDS + kk + achk) * 2;
        ldm_x4(sb + SO_AH + off, ah[mf]);
        ldm_x4(sb + SO_AL + off, al[mf]);
      }
#pragma unroll
      for (int nf = 0; nf < 4; ++nf) {
        uint32_t bh[2], bl[2];
        uint32_t off = so + (uint32_t)((wn + nf * 8 + brow) * DEC_LDS + kk + bchk) * 2;
        ldm_x2(sb + SO_BH + off, bh);
        ldm_x2(sb + SO_BL + off, bl);
#pragma unroll
        for (int mf = 0; mf < 4; ++mf) {
          mma16816(acc[mf][nf], ah[mf], bh);
          mma16816(acc[mf][nf], ah[mf], bl);
          mma16816(acc[mf][nf], al[mf], bh);
        }
      }
    }
    __syncthreads();
    if (kt + 2 < 16)
      dec_load(sb, kt & 1, kt + 2, m0, n0, tid, Ahi, Alo, Bhi, Blo);
  }

  const float* bsm = (const float*)(smem + SO_BIAS);
  const int rl = lane >> 2, cl = (lane & 3) * 2;
  if (!TRANSC) {
#pragma unroll
    for (int mf = 0; mf < 4; ++mf) {
      int r = m0 + wm + mf * 16 + rl;
#pragma unroll
      for (int nf = 0; nf < 4; ++nf) {
        int ci = wn + nf * 8 + cl;
        float b0 = bsm[ci], b1 = bsm[ci + 1];
        float2 v0 = make_float2(acc[mf][nf][0] + b0, acc[mf][nf][1] + b1);
        float2 v1 = make_float2(acc[mf][nf][2] + b0, acc[mf][nf][3] + b1);
        *(float2*)(C + (size_t)r * ldc + n0 + ci) = v0;
        *(float2*)(C + (size_t)(r + 8) * ldc + n0 + ci) = v1;
      }
    }
  } else {
#pragma unroll
    for (int mf = 0; mf < 4; ++mf) {
      int r = m0 + wm + mf * 16 + rl;
#pragma unroll
      for (int nf = 0; nf < 4; ++nf) {
        int ci = wn + nf * 8 + cl;
        float b0 = bsm[ci], b1 = bsm[ci + 1];
        C[(size_t)(n0 + ci) * ldc + r] = acc[mf][nf][0] + b0;
        C[(size_t)(n0 + ci + 1) * ldc + r] = acc[mf][nf][1] + b1;
        C[(size_t)(n0 + ci) * ldc + r + 8] = acc[mf][nf][2] + b0;
        C[(size_t)(n0 + ci + 1) * ldc + r + 8] = acc[mf][nf][3] + b1;
      }
    }
  }
}

// ------------------------- HMMA persistent LSTM ------------------------------
#define LW0 520
#define LW1 1032
#define LH  520
#define SO_W0HI 0
#define SO_W0LO 16640
#define SO_W1HI 33280
#define SO_W1LO 66304
#define SO_HHI  99328
#define SO_HLO  132608
#define SO_PS   165888
#define SO_ASM  198656
#define SO_B1S  202752
#define LSTM_SMEM 202816

__device__ __forceinline__ void gridbar() {
  __threadfence();
  __syncthreads();
  if (threadIdx.x == 0) {
    unsigned e = *(volatile unsigned*)&g_epoch;
    __threadfence();
    unsigned prev = atomicAdd(&g_count, 1u);
    if (prev == (unsigned)(LSTM_GRID - 1)) {
      atomicExch(&g_count, 0u);
      __threadfence();
      atomicAdd(&g_epoch, 1u);
    } else {
      while (*(volatile unsigned*)&g_epoch == e) __nanosleep(64);
    }
    __threadfence();
  }
  __syncthreads();
}

__device__ __forceinline__ void stage_split(char* smem, const float* __restrict__ src) {
  __nv_bfloat16* Hhi = (__nv_bfloat16*)(smem + SO_HHI);
  __nv_bfloat16* Hlo = (__nv_bfloat16*)(smem + SO_HLO);
  for (int i = threadIdx.x; i < 4096; i += 256) {
    int b = i >> 7;
    int k4 = (i & 127) << 2;
    float4 v = *(const float4*)(src + b * 512 + k4);
    __nv_bfloat162 h0, h1, l0, l1;
    h0.x = __float2bfloat16(v.x); l0.x = __float2bfloat16(v.x - __bfloat162float(h0.x));
    h0.y = __float2bfloat16(v.y); l0.y = __float2bfloat16(v.y - __bfloat162float(h0.y));
    h1.x = __float2bfloat16(v.z); l1.x = __float2bfloat16(v.z - __bfloat162float(h1.x));
    h1.y = __float2bfloat16(v.w); l1.y = __float2bfloat16(v.w - __bfloat162float(h1.y));
    *(__nv_bfloat162*)(Hhi + b * LH + k4) = h0;
    *(__nv_bfloat162*)(Hhi + b * LH + k4 + 2) = h1;
    *(__nv_bfloat162*)(Hlo + b * LH + k4) = l0;
    *(__nv_bfloat162*)(Hlo + b * LH + k4 + 2) = l1;
  }
}

__device__ __forceinline__ float sigm(float x) { return 1.f / (1.f + __expf(-x)); }

__global__ void __launch_bounds__(256, 1)
lstm_kernel(const float* __restrict__ fcW, const float* __restrict__ fcb,
            float* __restrict__ out) {
  extern __shared__ char smem[];
  uint32_t sb = smem_u32(smem);
  __nv_bfloat16* W0hi = (__nv_bfloat16*)(smem + SO_W0HI);
  __nv_bfloat16* W0lo = (__nv_bfloat16*)(smem + SO_W0LO);
  __nv_bfloat16* W1hi = (__nv_bfloat16*)(smem + SO_W1HI);
  __nv_bfloat16* W1lo = (__nv_bfloat16*)(smem + SO_W1LO);
  float* ps = (float*)(smem + SO_PS);
  float* a_sm = (float*)(smem + SO_ASM);
  float* b1s = (float*)(smem + SO_B1S);

  const int tid = threadIdx.x;
  const int w = tid >> 5;
  const int lane = tid & 31;
  const int cta = blockIdx.x;

  for (int i = tid; i < 16 * 512; i += 256) {
    int r = i >> 9, k = i & 511;
    int gr = cta * 4 + (r >> 2) + (r & 3) * 512;
    float v = fcW[(size_t)gr * 1024 + 512 + k];
    __nv_bfloat16 h = __float2bfloat16(v);
    W0hi[r * LW0 + k] = h;
    W0lo[r * LW0 + k] = __float2bfloat16(v - __bfloat162float(h));
  }
  for (int i = tid; i < 16 * 1024; i += 256) {
    int r = i >> 10, k = i & 1023;
    int gr = cta * 4 + (r >> 2) + (r & 3) * 512;
    float v = fcW[(size_t)2048 * 1024 + (size_t)gr * 1024 + k];
    __nv_bfloat16 h = __float2bfloat16(v);
    W1hi[r * LW1 + k] = h;
    W1lo[r * LW1 + k] = __float2bfloat16(v - __bfloat162float(h));
  }
  if (tid < 16)
    b1s[tid] = fcb[2048 + cta * 4 + (tid >> 2) + (tid & 3) * 512];

  {
    int g = cta * 256 + tid;
    if (g < BATCH * NHID) {
      g_h0[0][g] = 0.f; g_h0[1][g] = 0.f;
      g_h1[0][g] = 0.f; g_h1[1][g] = 0.f;
    }
  }
  gridbar();

  float c0r = 0.f, c1r = 0.f;
  const int U = cta * 4 + (w & 3);
  float* hid = out + HID_OFF;

  const int arow = lane & 15, achk = (lane >> 4) * 8;
  const int brow = lane & 7, bchk = ((lane >> 3) & 1) * 8;
  const int rl = lane >> 2, cl = (lane & 3) * 2;

#pragma unroll 1
  for (int p = 0; p <= SEQ; ++p) {
    const int wp = p & 1;

    float xg[4] = {0.f, 0.f, 0.f, 0.f};
    if (w < 4 && p < SEQ) {
#pragma unroll
      for (int g = 0; g < 4; ++g)
        xg[g] = g_g0xT[(size_t)(U + g * 512) * M_ROWS + p * 32 + lane];
    }

    float acc0[2][2][4], acc1[2][2][4];
#pragma unroll
    for (int i = 0; i < 2; i++)
#pragma unroll
      for (int j = 0; j < 2; j++)
#pragma unroll
        for (int v = 0; v < 4; v++) { acc0[i][j][v] = 0.f; acc1[i][j][v] = 0.f; }

    stage_split(smem, &g_h0[wp ^ 1][0]);
    __syncthreads();
#pragma unroll
    for (int kt = 0; kt < 4; ++kt) {
      const int kk = (w * 4 + kt) * 16;
      uint32_t ah[2][4], al[2][4], b0h[2][2], b0l[2][2], b1h[2][2], b1l[2][2];
#pragma unroll
      for (int mf = 0; mf < 2; ++mf) {
        uint32_t off = (uint32_t)((mf * 16 + arow) * LH + kk + achk) * 2;
        ldm_x4(sb + SO_HHI + off, ah[mf]);
        ldm_x4(sb + SO_HLO + off, al[mf]);
      }
#pragma unroll
      for (int nf = 0; nf < 2; ++nf) {
        uint32_t o0 = (uint32_t)((nf * 8 + brow) * LW0 + kk + bchk) * 2;
        ldm_x2(sb + SO_W0HI + o0, b0h[nf]);
        ldm_x2(sb + SO_W0LO + o0, b0l[nf]);
        uint32_t o1 = (uint32_t)((nf * 8 + brow) * LW1 + kk + bchk) * 2;
        ldm_x2(sb + SO_W1HI + o1, b1h[nf]);
        ldm_x2(sb + SO_W1LO + o1, b1l[nf]);
      }
#pragma unroll
      for (int mf = 0; mf < 2; ++mf)
#pragma unroll
        for (int nf = 0; nf < 2; ++nf) {
          mma16816(acc0[mf][nf], ah[mf], b0h[nf]);
          mma16816(acc0[mf][nf], ah[mf], b0l[nf]);
          mma16816(acc0[mf][nf], al[mf], b0h[nf]);
          mma16816(acc1[mf][nf], ah[mf], b1h[nf]);
          mma16816(acc1[mf][nf], ah[mf], b1l[nf]);
          mma16816(acc1[mf][nf], al[mf], b1h[nf]);
        }
    }
    __syncthreads();

    stage_split(smem, &g_h1[wp ^ 1][0]);
    __syncthreads();
#pragma unroll
    for (int kt = 0; kt < 4; ++kt) {
      const int kk = (w * 4 + kt) * 16;
      uint32_t ah[2][4], al[2][4], b1h[2][2], b1l[2][2];
#pragma unroll
      for (int mf = 0; mf < 2; ++mf) {
        uint32_t off = (uint32_t)((mf * 16 + arow) * LH + kk + achk) * 2;
        ldm_x4(sb + SO_HHI + off, ah[mf]);
        ldm_x4(sb + SO_HLO + off, al[mf]);
      }
#pragma unroll
      for (int nf = 0; nf < 2; ++nf) {
        uint32_t o1 = (uint32_t)((nf * 8 + brow) * LW1 + 512 + kk + bchk) * 2;
        ldm_x2(sb + SO_W1HI + o1, b1h[nf]);
        ldm_x2(sb + SO_W1LO + o1, b1l[nf]);
      }
#pragma unroll
      for (int mf = 0; mf < 2; ++mf)
#pragma unroll
        for (int nf = 0; nf < 2; ++nf) {
          mma16816(acc1[mf][nf], ah[mf], b1h[nf]);
          mma16816(acc1[mf][nf], ah[mf], b1l[nf]);
          mma16816(acc1[mf][nf], al[mf], b1h[nf]);
        }
    }

#pragma unroll
    for (int mf = 0; mf < 2; ++mf)
#pragma unroll
      for (int nf = 0; nf < 2; ++nf)
#pragma unroll
        for (int v = 0; v < 4; ++v) {
          int b = mf * 16 + rl + ((v & 2) ? 8 : 0);
          int n = nf * 8 + cl + (v & 1);
          ps[(w * 32 + n) * 32 + b] = acc0[mf][nf][v];
          ps[(w * 32 + 16 + n) * 32 + b] = acc1[mf][nf][v];
        }
    __syncthreads();

#pragma unroll
    for (int q = 0; q < 4; ++q) {
      int o = tid + q * 256;
      int n = o >> 5, b = o & 31;
      float s = 0.f;
#pragma unroll
      for (int ww = 0; ww < 8; ++ww) s += ps[(ww * 32 + n) * 32 + b];
      a_sm[n * 32 + b] = s;
    }
    __syncthreads();

    if (w < 4) {
      if (p < SEQ) {
        float a[4];
#pragma unroll
        for (int g = 0; g < 4; ++g)
          a[g] = a_sm[(w * 4 + g) * 32 + lane] + xg[g];
        float ig = sigm(a[0]), fg = sigm(a[1]), og = sigm(a[2]);
        float bg = tanhf(a[3]);
        c0r = fg * c0r + ig * bg;
        float h0v = og * tanhf(c0r);
        g_h0[wp][lane * 512 + U] = h0v;
        if (p == SEQ - 1) hid[lane * 512 + U] = h0v;
      }
    } else {
      if (p >= 1) {
        float a[4];
#pragma unroll
        for (int g = 0; g < 4; ++g)
          a[g] = a_sm[(16 + (w - 4) * 4 + g) * 32 + lane] + b1s[(w - 4) * 4 + g];
        float ig = sigm(a[0]), fg = sigm(a[1]), og = sigm(a[2]);
        float bg = tanhf(a[3]);
        c1r = fg * c1r + ig * bg;
        float h1v = og * tanhf(c1r);
        g_h1[wp][lane * 512 + U] = h1v;
        g_outT[(size_t)U * M_ROWS + (p - 1) * 32 + lane] = h1v;
        if (p == SEQ) hid[16384 + lane * 512 + U] = h1v;
      }
    }
    gridbar();
  }
}

// ------------------------- launch ------------------------------------------
extern "C" void kernel_launch(void* const* d_in, const int* in_sizes, int n_in,
                              void* d_out, int out_size) {
  const int* tok = (const int*)d_in[0];
  const float* embW = (const float*)d_in[1];
  const float* fcW = (const float*)d_in[2];
  const float* fcb = (const float*)d_in[3];
  const float* decW = (const float*)d_in[4];
  const float* decb = (const float*)d_in[5];
  float* out = (float*)d_out;

  void *p_g0xT = 0, *p_Ehi = 0, *p_Elo = 0, *p_W0hi = 0, *p_W0lo = 0;
  void *p_Ahi = 0, *p_Alo = 0, *p_Bhi = 0, *p_Blo = 0;
  cudaGetSymbolAddress(&p_g0xT, g_g0xT);
  cudaGetSymbolAddress(&p_Ehi, g_Ehi);
  cudaGetSymbolAddress(&p_Elo, g_Elo);
  cudaGetSymbolAddress(&p_W0hi, g_W0hi);
  cudaGetSymbolAddress(&p_W0lo, g_W0lo);
  cudaGetSymbolAddress(&p_Ahi, g_Ahi);
  cudaGetSymbolAddress(&p_Alo, g_Alo);
  cudaGetSymbolAddress(&p_Bhi, g_Bhi);
  cudaGetSymbolAddress(&p_Blo, g_Blo);

  cudaFuncSetAttribute(mma_gemm<false>,
                       cudaFuncAttributeMaxDynamicSharedMemorySize, DEC_SMEM);
  cudaFuncSetAttribute(mma_gemm<true>,
                       cudaFuncAttributeMaxDynamicSharedMemorySize, DEC_SMEM);
  cudaFuncSetAttribute(lstm_kernel,
                       cudaFuncAttributeMaxDynamicSharedMemorySize, LSTM_SMEM);

  // 1) embedding gather -> split bf16 row-major
  embed_kernel<<<(M_ROWS * NHID + 255) / 256, 256>>>(tok, embW);

  // 2) weight splits
  convW0_kernel<<<(2048 * NHID + 255) / 256, 256>>>(fcW);
  convB_kernel<<<(NVOC * NHID + 255) / 256, 256>>>(decW);

  // 3) layer-0 input projection (HMMA): g0xT[n][m] = emb . W0^T + b0
  mma_gemm<true><<<dim3(M_ROWS / 128, 2048 / 128), 256, DEC_SMEM>>>(
      (const __nv_bfloat16*)p_Ehi, (const __nv_bfloat16*)p_Elo,
      (const __nv_bfloat16*)p_W0hi, (const __nv_bfloat16*)p_W0lo,
      fcb, (float*)p_g0xT, M_ROWS);

  // 4) persistent HMMA LSTM recurrence
  lstm_kernel<<<LSTM_GRID, 256, LSTM_SMEM>>>(fcW, fcb, out);

  // 5) transpose + split h1 activations to bf16
  convA_kernel<<<dim3(NHID / 32, M_ROWS / 32), dim3(32, 8)>>>();

  // 6) HMMA decoder GEMM
  mma_gemm<false><<<dim3(M_ROWS / 128, NVOC / 128), 256, DEC_SMEM>>>(
      (const __nv_bfloat16*)p_Ahi, (const __nv_bfloat16*)p_Alo,
      (const __nv_bfloat16*)p_Bhi, (const __nv_bfloat16*)p_Blo,
      decb, out, NVOC);
}

// round 10
// speedup vs baseline: 2.5441x; 1.0553x over previous
#include <cuda_runtime.h>
#include <cuda_bf16.h>
#include <math.h>
#include <stdint.h>

#define SEQ 128
#define BATCH 32
#define NHID 512
#define NVOC 32000
#define M_ROWS (SEQ * BATCH)                 /* 4096 */
#define HID_OFF ((size_t)M_ROWS * NVOC)      /* 131072000 */
#define LSTM_GRID 128

// ------------------------- device scratch (no allocs allowed) ----------------
__device__ float g_g0xT[(size_t)4 * NHID * M_ROWS];   // layer0 x-gates^T [2048][4096]
__device__ float g_h0[2][BATCH * NHID];
__device__ float g_h1[2][BATCH * NHID];
__device__ unsigned g_count = 0;
__device__ unsigned g_epoch = 0;

// split-bf16 operands
__device__ __nv_bfloat16 g_Ehi[(size_t)M_ROWS * NHID];   // emb  [m][k]
__device__ __nv_bfloat16 g_Elo[(size_t)M_ROWS * NHID];
__device__ __nv_bfloat16 g_W0hi[(size_t)2048 * NHID];    // fcW0 x-part [n][k]
__device__ __nv_bfloat16 g_W0lo[(size_t)2048 * NHID];
__device__ __nv_bfloat16 g_Ahi[(size_t)M_ROWS * NHID];   // h1 out [m][k]
__device__ __nv_bfloat16 g_Alo[(size_t)M_ROWS * NHID];
__device__ __nv_bfloat16 g_Bhi[(size_t)NVOC * NHID];     // decW  [n][k]
__device__ __nv_bfloat16 g_Blo[(size_t)NVOC * NHID];

// ------------------------- shared PTX helpers --------------------------------
__device__ __forceinline__ uint32_t smem_u32(const void* p) {
  uint32_t a;
  asm("{ .reg .u64 t; cvta.to.shared.u64 t, %1; cvt.u32.u64 %0, t; }"
      : "=r"(a) : "l"(p));
  return a;
}
__device__ __forceinline__ void cp16(uint32_t dst, const void* src) {
  asm volatile("cp.async.cg.shared.global [%0], [%1], 16;\n" ::"r"(dst), "l"(src));
}
__device__ __forceinline__ void ldm_x4(uint32_t a, uint32_t* r) {
  asm volatile("ldmatrix.sync.aligned.m8n8.x4.shared.b16 {%0,%1,%2,%3}, [%4];"
               : "=r"(r[0]), "=r"(r[1]), "=r"(r[2]), "=r"(r[3]) : "r"(a));
}
__device__ __forceinline__ void ldm_x2(uint32_t a, uint32_t* r) {
  asm volatile("ldmatrix.sync.aligned.m8n8.x2.shared.b16 {%0,%1}, [%2];"
               : "=r"(r[0]), "=r"(r[1]) : "r"(a));
}
__device__ __forceinline__ void mma16816(float* c, const uint32_t* a,
                                         const uint32_t* b) {
  asm volatile(
      "mma.sync.aligned.m16n8k16.row.col.f32.bf16.bf16.f32 "
      "{%0,%1,%2,%3}, {%4,%5,%6,%7}, {%8,%9}, {%0,%1,%2,%3};"
      : "+f"(c[0]), "+f"(c[1]), "+f"(c[2]), "+f"(c[3])
      : "r"(a[0]), "r"(a[1]), "r"(a[2]), "r"(a[3]), "r"(b[0]), "r"(b[1]));
}

// ------------------------- embedding gather (split bf16, row-major) ----------
__global__ void embed_kernel(const int* __restrict__ tok,
                             const float* __restrict__ embW) {
  int idx = blockIdx.x * 256 + threadIdx.x;
  if (idx >= M_ROWS * NHID) return;
  int m = idx >> 9;
  int k = idx & 511;
  float v = embW[(size_t)tok[m] * NHID + k];
  __nv_bfloat16 h = __float2bfloat16(v);
  g_Ehi[idx] = h;
  g_Elo[idx] = __float2bfloat16(v - __bfloat162float(h));
}

// ------------------------- weight split conversions --------------------------
__global__ void convW0_kernel(const float* __restrict__ fcW) {
  int i = blockIdx.x * 256 + threadIdx.x;
  if (i >= 2048 * NHID) return;
  int n = i >> 9, k = i & 511;
  float x = fcW[(size_t)n * 1024 + k];
  __nv_bfloat16 h = __float2bfloat16(x);
  g_W0hi[i] = h;
  g_W0lo[i] = __float2bfloat16(x - __bfloat162float(h));
}

__global__ void convB_kernel(const float* __restrict__ W) {
  int i = blockIdx.x * 256 + threadIdx.x;
  if (i >= NVOC * NHID) return;
  float x = W[i];
  __nv_bfloat16 h = __float2bfloat16(x);
  g_Bhi[i] = h;
  g_Blo[i] = __float2bfloat16(x - __bfloat162float(h));
}

// ------------------------- HMMA GEMM (decoder + gemm0) -----------------------
// C = A(split) . B(split)^T + bias ; 3-term split-bf16, K=512.
// Tile 128x128, 8 warps (2x4), warp 64x32, BK=32, 3-stage cp.async, 2 CTA/SM.
// SMEM row (128B, SW128 swizz): [ hi k0..31 | lo k0..31 ] per matrix row.
#define STG 32768                       /* per-stage bytes: A 16K + B 16K */
#define SO_BUF 1024
#define DEC_SMEM (1024 + 3 * STG)       /* 99328 */

__device__ __forceinline__ void dec_load(uint32_t sb, int s, int kt,
                                         int m0, int n0, int tid,
                                         const __nv_bfloat16* Ahi,
                                         const __nv_bfloat16* Alo,
                                         const __nv_bfloat16* Bhi,
                                         const __nv_bfloat16* Blo) {
  const int k0 = kt * 32;
  const uint32_t base = sb + SO_BUF + (uint32_t)s * STG;
#pragma unroll
  for (int i = tid; i < 1024; i += 256) {
    int row = i >> 3, c = i & 7;
    uint32_t phys = base + row * 128 + ((c ^ (row & 7)) << 4);
    size_t goff = (size_t)k0 + (c & 3) * 8;
    const __nv_bfloat16* asrc =
        (c < 4 ? Ahi : Alo) + (size_t)(m0 + row) * NHID + goff;
    cp16(phys, asrc);
    const __nv_bfloat16* bsrc =
        (c < 4 ? Bhi : Blo) + (size_t)(n0 + row) * NHID + goff;
    cp16(phys + 16384, bsrc);
  }
  asm volatile("cp.async.commit_group;\n" ::: "memory");
}

template <bool TRANSC>
__global__ void __launch_bounds__(256, 2)
mma_gemm(const __nv_bfloat16* __restrict__ Ahi,
         const __nv_bfloat16* __restrict__ Alo,
         const __nv_bfloat16* __restrict__ Bhi,
         const __nv_bfloat16* __restrict__ Blo,
         const float* __restrict__ bias, float* __restrict__ C, int ldc) {
  extern __shared__ char smem[];
  uint32_t sb = smem_u32(smem);
  const int tid = threadIdx.x;
  const int wid = tid >> 5;
  const int lane = tid & 31;
  const int m0 = blockIdx.x * 128;
  const int n0 = blockIdx.y * 128;
  const int wm = (wid >> 2) * 64;
  const int wn = (wid & 3) * 32;

  if (tid < 128) ((float*)smem)[tid] = bias[n0 + tid];

  float acc[4][4][4];
#pragma unroll
  for (int i = 0; i < 4; i++)
#pragma unroll
    for (int j = 0; j < 4; j++)
#pragma unroll
      for (int v = 0; v < 4; v++) acc[i][j][v] = 0.f;

  dec_load(sb, 0, 0, m0, n0, tid, Ahi, Alo, Bhi, Blo);
  dec_load(sb, 1, 1, m0, n0, tid, Ahi, Alo, Bhi, Blo);

  // per-lane fragment coordinates (logical; swizzle applied per-address)
  const int arow = lane & 15;            // A: x4 uses 16 rows
  const int ahalf = lane >> 4;           // A: which 16B half of k16 window
  const int brow = lane & 7;             // B: x2 uses 8 rows
  const int bhalf = (lane >> 3) & 1;
  const int aswz = arow & 7;

  int s_cur = 0, s_nxt = 2;              // stage of kt, stage of kt+2
#pragma unroll 1
  for (int kt = 0; kt < 16; ++kt) {
    if (kt == 15)
      asm volatile("cp.async.wait_group 0;\n" ::: "memory");
    else
      asm volatile("cp.async.wait_group 1;\n" ::: "memory");
    __syncthreads();

    if (kt + 2 < 16)
      dec_load(sb, s_nxt, kt + 2, m0, n0, tid, Ahi, Alo, Bhi, Blo);

    const uint32_t abase = sb + SO_BUF + (uint32_t)s_cur * STG;
    const uint32_t bbase = abase + 16384;

#pragma unroll
    for (int ks = 0; ks < 2; ++ks) {
      uint32_t ah[4][4], al[4][4];
      const int achunk = (ks * 2 + ahalf) ^ aswz;   // swizzled 16B chunk
#pragma unroll
      for (int mf = 0; mf < 4; ++mf) {
        uint32_t addr = abase + (uint32_t)(wm + mf * 16 + arow) * 128 +
                        (achunk << 4);
        ldm_x4(addr, ah[mf]);
        ldm_x4(addr ^ 64, al[mf]);                  // lo half: chunk+4
      }
      const int bchunk = (ks * 2 + bhalf) ^ brow;
#pragma unroll
      for (int nf = 0; nf < 4; ++nf) {
        uint32_t bh[2], bl[2];
        uint32_t addr = bbase + (uint32_t)(wn + nf * 8 + brow) * 128 +
                        (bchunk << 4);
        ldm_x2(addr, bh);
        ldm_x2(addr ^ 64, bl);
#pragma unroll
        for (int mf = 0; mf < 4; ++mf) {
          mma16816(acc[mf][nf], ah[mf], bh);
          mma16816(acc[mf][nf], ah[mf], bl);
          mma16816(acc[mf][nf], al[mf], bh);
        }
      }
    }
    s_cur = s_cur == 2 ? 0 : s_cur + 1;
    s_nxt = s_nxt == 2 ? 0 : s_nxt + 1;
  }

  const float* bsm = (const float*)smem;
  const int rl = lane >> 2, cl = (lane & 3) * 2;
  if (!TRANSC) {
#pragma unroll
    for (int mf = 0; mf < 4; ++mf) {
      int r = m0 + wm + mf * 16 + rl;
#pragma unroll
      for (int nf = 0; nf < 4; ++nf) {
        int ci = wn + nf * 8 + cl;
        float b0 = bsm[ci], b1 = bsm[ci + 1];
        float2 v0 = make_float2(acc[mf][nf][0] + b0, acc[mf][nf][1] + b1);
        float2 v1 = make_float2(acc[mf][nf][2] + b0, acc[mf][nf][3] + b1);
        *(float2*)(C + (size_t)r * ldc + n0 + ci) = v0;
        *(float2*)(C + (size_t)(r + 8) * ldc + n0 + ci) = v1;
      }
    }
  } else {
#pragma unroll
    for (int mf = 0; mf < 4; ++mf) {
      int r = m0 + wm + mf * 16 + rl;
#pragma unroll
      for (int nf = 0; nf < 4; ++nf) {
        int ci = wn + nf * 8 + cl;
        float b0 = bsm[ci], b1 = bsm[ci + 1];
        C[(size_t)(n0 + ci) * ldc + r] = acc[mf][nf][0] + b0;
        C[(size_t)(n0 + ci + 1) * ldc + r] = acc[mf][nf][1] + b1;
        C[(size_t)(n0 + ci) * ldc + r + 8] = acc[mf][nf][2] + b0;
        C[(size_t)(n0 + ci + 1) * ldc + r + 8] = acc[mf][nf][3] + b1;
      }
    }
  }
}

// ------------------------- HMMA persistent LSTM ------------------------------
#define LW0 520
#define LW1 1032
#define LH  520
#define SO_W0HI 0
#define SO_W0LO 16640
#define SO_W1HI 33280
#define SO_W1LO 66304
#define SO_HHI  99328
#define SO_HLO  132608
#define SO_PS   165888
#define SO_ASM  198656
#define SO_B1S  202752
#define LSTM_SMEM 202816

__device__ __forceinline__ void gridbar() {
  __threadfence();
  __syncthreads();
  if (threadIdx.x == 0) {
    unsigned e = *(volatile unsigned*)&g_epoch;
    __threadfence();
    unsigned prev = atomicAdd(&g_count, 1u);
    if (prev == (unsigned)(LSTM_GRID - 1)) {
      atomicExch(&g_count, 0u);
      __threadfence();
      atomicAdd(&g_epoch, 1u);
    } else {
      while (*(volatile unsigned*)&g_epoch == e) __nanosleep(64);
    }
    __threadfence();
  }
  __syncthreads();
}

__device__ __forceinline__ void stage_split(char* smem, const float* __restrict__ src) {
  __nv_bfloat16* Hhi = (__nv_bfloat16*)(smem + SO_HHI);
  __nv_bfloat16* Hlo = (__nv_bfloat16*)(smem + SO_HLO);
  for (int i = threadIdx.x; i < 4096; i += 256) {
    int b = i >> 7;
    int k4 = (i & 127) << 2;
    float4 v = *(const float4*)(src + b * 512 + k4);
    __nv_bfloat162 h0, h1, l0, l1;
    h0.x = __float2bfloat16(v.x); l0.x = __float2bfloat16(v.x - __bfloat162float(h0.x));
    h0.y = __float2bfloat16(v.y); l0.y = __float2bfloat16(v.y - __bfloat162float(h0.y));
    h1.x = __float2bfloat16(v.z); l1.x = __float2bfloat16(v.z - __bfloat162float(h1.x));
    h1.y = __float2bfloat16(v.w); l1.y = __float2bfloat16(v.w - __bfloat162float(h1.y));
    *(__nv_bfloat162*)(Hhi + b * LH + k4) = h0;
    *(__nv_bfloat162*)(Hhi + b * LH + k4 + 2) = h1;
    *(__nv_bfloat162*)(Hlo + b * LH + k4) = l0;
    *(__nv_bfloat162*)(Hlo + b * LH + k4 + 2) = l1;
  }
}

__device__ __forceinline__ float sigm(float x) { return 1.f / (1.f + __expf(-x)); }

__global__ void __launch_bounds__(256, 1)
lstm_kernel(const float* __restrict__ fcW, const float* __restrict__ fcb,
            float* __restrict__ out) {
  extern __shared__ char smem[];
  uint32_t sb = smem_u32(smem);
  __nv_bfloat16* W0hi = (__nv_bfloat16*)(smem + SO_W0HI);
  __nv_bfloat16* W0lo = (__nv_bfloat16*)(smem + SO_W0LO);
  __nv_bfloat16* W1hi = (__nv_bfloat16*)(smem + SO_W1HI);
  __nv_bfloat16* W1lo = (__nv_bfloat16*)(smem + SO_W1LO);
  float* ps = (float*)(smem + SO_PS);
  float* a_sm = (float*)(smem + SO_ASM);
  float* b1s = (float*)(smem + SO_B1S);

  const int tid = threadIdx.x;
  const int w = tid >> 5;
  const int lane = tid & 31;
  const int cta = blockIdx.x;

  for (int i = tid; i < 16 * 512; i += 256) {
    int r = i >> 9, k = i & 511;
    int gr = cta * 4 + (r >> 2) + (r & 3) * 512;
    float v = fcW[(size_t)gr * 1024 + 512 + k];
    __nv_bfloat16 h = __float2bfloat16(v);
    W0hi[r * LW0 + k] = h;
    W0lo[r * LW0 + k] = __float2bfloat16(v - __bfloat162float(h));
  }
  for (int i = tid; i < 16 * 1024; i += 256) {
    int r = i >> 10, k = i & 1023;
    int gr = cta * 4 + (r >> 2) + (r & 3) * 512;
    float v = fcW[(size_t)2048 * 1024 + (size_t)gr * 1024 + k];
    __nv_bfloat16 h = __float2bfloat16(v);
    W1hi[r * LW1 + k] = h;
    W1lo[r * LW1 + k] = __float2bfloat16(v - __bfloat162float(h));
  }
  if (tid < 16)
    b1s[tid] = fcb[2048 + cta * 4 + (tid >> 2) + (tid & 3) * 512];

  {
    int g = cta * 256 + tid;
    if (g < BATCH * NHID) {
      g_h0[0][g] = 0.f; g_h0[1][g] = 0.f;
      g_h1[0][g] = 0.f; g_h1[1][g] = 0.f;
    }
  }
  gridbar();

  float c0r = 0.f, c1r = 0.f;
  const int U = cta * 4 + (w & 3);
  float* hid = out + HID_OFF;

  const int arow = lane & 15, achk = (lane >> 4) * 8;
  const int brow = lane & 7, bchk = ((lane >> 3) & 1) * 8;
  const int rl = lane >> 2, cl = (lane & 3) * 2;

#pragma unroll 1
  for (int p = 0; p <= SEQ; ++p) {
    const int wp = p & 1;

    float xg[4] = {0.f, 0.f, 0.f, 0.f};
    if (w < 4 && p < SEQ) {
#pragma unroll
      for (int g = 0; g < 4; ++g)
        xg[g] = g_g0xT[(size_t)(U + g * 512) * M_ROWS + p * 32 + lane];
    }

    float acc0[2][2][4], acc1[2][2][4];
#pragma unroll
    for (int i = 0; i < 2; i++)
#pragma unroll
      for (int j = 0; j < 2; j++)
#pragma unroll
        for (int v = 0; v < 4; v++) { acc0[i][j][v] = 0.f; acc1[i][j][v] = 0.f; }

    stage_split(smem, &g_h0[wp ^ 1][0]);
    __syncthreads();
#pragma unroll
    for (int kt = 0; kt < 4; ++kt) {
      const int kk = (w * 4 + kt) * 16;
      uint32_t ah[2][4], al[2][4], b0h[2][2], b0l[2][2], b1h[2][2], b1l[2][2];
#pragma unroll
      for (int mf = 0; mf < 2; ++mf) {
        uint32_t off = (uint32_t)((mf * 16 + arow) * LH + kk + achk) * 2;
        ldm_x4(sb + SO_HHI + off, ah[mf]);
        ldm_x4(sb + SO_HLO + off, al[mf]);
      }
#pragma unroll
      for (int nf = 0; nf < 2; ++nf) {
        uint32_t o0 = (uint32_t)((nf * 8 + brow) * LW0 + kk + bchk) * 2;
        ldm_x2(sb + SO_W0HI + o0, b0h[nf]);
        ldm_x2(sb + SO_W0LO + o0, b0l[nf]);
        uint32_t o1 = (uint32_t)((nf * 8 + brow) * LW1 + kk + bchk) * 2;
        ldm_x2(sb + SO_W1HI + o1, b1h[nf]);
        ldm_x2(sb + SO_W1LO + o1, b1l[nf]);
      }
#pragma unroll
      for (int mf = 0; mf < 2; ++mf)
#pragma unroll
        for (int nf = 0; nf < 2; ++nf) {
          mma16816(acc0[mf][nf], ah[mf], b0h[nf]);
          mma16816(acc0[mf][nf], ah[mf], b0l[nf]);
          mma16816(acc0[mf][nf], al[mf], b0h[nf]);
          mma16816(acc1[mf][nf], ah[mf], b1h[nf]);
          mma16816(acc1[mf][nf], ah[mf], b1l[nf]);
          mma16816(acc1[mf][nf], al[mf], b1h[nf]);
        }
    }
    __syncthreads();

    stage_split(smem, &g_h1[wp ^ 1][0]);
    __syncthreads();
#pragma unroll
    for (int kt = 0; kt < 4; ++kt) {
      const int kk = (w * 4 + kt) * 16;
      uint32_t ah[2][4], al[2][4], b1h[2][2], b1l[2][2];
#pragma unroll
      for (int mf = 0; mf < 2; ++mf) {
        uint32_t off = (uint32_t)((mf * 16 + arow) * LH + kk + achk) * 2;
        ldm_x4(sb + SO_HHI + off, ah[mf]);
        ldm_x4(sb + SO_HLO + off, al[mf]);
      }
#pragma unroll
      for (int nf = 0; nf < 2; ++nf) {
        uint32_t o1 = (uint32_t)((nf * 8 + brow) * LW1 + 512 + kk + bchk) * 2;
        ldm_x2(sb + SO_W1HI + o1, b1h[nf]);
        ldm_x2(sb + SO_W1LO + o1, b1l[nf]);
      }
#pragma unroll
      for (int mf = 0; mf < 2; ++mf)
#pragma unroll
        for (int nf = 0; nf < 2; ++nf) {
          mma16816(acc1[mf][nf], ah[mf], b1h[nf]);
          mma16816(acc1[mf][nf], ah[mf], b1l[nf]);
          mma16816(acc1[mf][nf], al[mf], b1h[nf]);
        }
    }

#pragma unroll
    for (int mf = 0; mf < 2; ++mf)
#pragma unroll
      for (int nf = 0; nf < 2; ++nf)
#pragma unroll
        for (int v = 0; v < 4; ++v) {
          int b = mf * 16 + rl + ((v & 2) ? 8 : 0);
          int n = nf * 8 + cl + (v & 1);
          ps[(w * 32 + n) * 32 + b] = acc0[mf][nf][v];
          ps[(w * 32 + 16 + n) * 32 + b] = acc1[mf][nf][v];
        }
    __syncthreads();

#pragma unroll
    for (int q = 0; q < 4; ++q) {
      int o = tid + q * 256;
      int n = o >> 5, b = o & 31;
      float s = 0.f;
#pragma unroll
      for (int ww = 0; ww < 8; ++ww) s += ps[(ww * 32 + n) * 32 + b];
      a_sm[n * 32 + b] = s;
    }
    __syncthreads();

    if (w < 4) {
      if (p < SEQ) {
        float a[4];
#pragma unroll
        for (int g = 0; g < 4; ++g)
          a[g] = a_sm[(w * 4 + g) * 32 + lane] + xg[g];
        float ig = sigm(a[0]), fg = sigm(a[1]), og = sigm(a[2]);
        float bg = tanhf(a[3]);
        c0r = fg * c0r + ig * bg;
        float h0v = og * tanhf(c0r);
        g_h0[wp][lane * 512 + U] = h0v;
        if (p == SEQ - 1) hid[lane * 512 + U] = h0v;
      }
    } else {
      if (p >= 1) {
        float a[4];
#pragma unroll
        for (int g = 0; g < 4; ++g)
          a[g] = a_sm[(16 + (w - 4) * 4 + g) * 32 + lane] + b1s[(w - 4) * 4 + g];
        float ig = sigm(a[0]), fg = sigm(a[1]), og = sigm(a[2]);
        float bg = tanhf(a[3]);
        c1r = fg * c1r + ig * bg;
        float h1v = og * tanhf(c1r);
        g_h1[wp][lane * 512 + U] = h1v;
        // fused convA: write split-bf16 decoder A operand directly
        {
          size_t o = (size_t)((p - 1) * 32 + lane) * NHID + U;
          __nv_bfloat16 hh = __float2bfloat16(h1v);
          g_Ahi[o] = hh;
          g_Alo[o] = __float2bfloat16(h1v - __bfloat162float(hh));
        }
        if (p == SEQ) hid[16384 + lane * 512 + U] = h1v;
      }
    }
    gridbar();
  }
}

// ------------------------- launch ------------------------------------------
extern "C" void kernel_launch(void* const* d_in, const int* in_sizes, int n_in,
                              void* d_out, int out_size) {
  const int* tok = (const int*)d_in[0];
  const float* embW = (const float*)d_in[1];
  const float* fcW = (const float*)d_in[2];
  const float* fcb = (const float*)d_in[3];
  const float* decW = (const float*)d_in[4];
  const float* decb = (const float*)d_in[5];
  float* out = (float*)d_out;

  void *p_g0xT = 0, *p_Ehi = 0, *p_Elo = 0, *p_W0hi = 0, *p_W0lo = 0;
  void *p_Ahi = 0, *p_Alo = 0, *p_Bhi = 0, *p_Blo = 0;
  cudaGetSymbolAddress(&p_g0xT, g_g0xT);
  cudaGetSymbolAddress(&p_Ehi, g_Ehi);
  cudaGetSymbolAddress(&p_Elo, g_Elo);
  cudaGetSymbolAddress(&p_W0hi, g_W0hi);
  cudaGetSymbolAddress(&p_W0lo, g_W0lo);
  cudaGetSymbolAddress(&p_Ahi, g_Ahi);
  cudaGetSymbolAddress(&p_Alo, g_Alo);
  cudaGetSymbolAddress(&p_Bhi, g_Bhi);
  cudaGetSymbolAddress(&p_Blo, g_Blo);

  cudaFuncSetAttribute(mma_gemm<false>,
                       cudaFuncAttributeMaxDynamicSharedMemorySize, DEC_SMEM);
  cudaFuncSetAttribute(mma_gemm<true>,
                       cudaFuncAttributeMaxDynamicSharedMemorySize, DEC_SMEM);
  cudaFuncSetAttribute(lstm_kernel,
                       cudaFuncAttributeMaxDynamicSharedMemorySize, LSTM_SMEM);

  // 1) embedding gather -> split bf16 row-major
  embed_kernel<<<(M_ROWS * NHID + 255) / 256, 256>>>(tok, embW);

  // 2) weight splits
  convW0_kernel<<<(2048 * NHID + 255) / 256, 256>>>(fcW);
  convB_kernel<<<(NVOC * NHID + 255) / 256, 256>>>(decW);

  // 3) layer-0 input projection (HMMA): g0xT[n][m] = emb . W0^T + b0
  mma_gemm<true><<<dim3(M_ROWS / 128, 2048 / 128), 256, DEC_SMEM>>>(
      (const __nv_bfloat16*)p_Ehi, (const __nv_bfloat16*)p_Elo,
      (const __nv_bfloat16*)p_W0hi, (const __nv_bfloat16*)p_W0lo,
      fcb, (float*)p_g0xT, M_ROWS);

  // 4) persistent HMMA LSTM recurrence (writes split-bf16 A directly)
  lstm_kernel<<<LSTM_GRID, 256, LSTM_SMEM>>>(fcW, fcb, out);

  // 5) HMMA decoder GEMM
  mma_gemm<false><<<dim3(M_ROWS / 128, NVOC / 128), 256, DEC_SMEM>>>(
      (const __nv_bfloat16*)p_Ahi, (const __nv_bfloat16*)p_Alo,
      (const __nv_bfloat16*)p_Bhi, (const __nv_bfloat16*)p_Blo,
      decb, out, NVOC);
}